// round 7
// baseline (speedup 1.0000x reference)
#include <cuda_runtime.h>
#include <cuda_bf16.h>
#include <math_constants.h>

// ---------------- shapes ----------------
// B=16, A=5 -> N = 80 folded batch
// conv0: 4->32 k5 p1 : 45 -> 43 -> pool 21
// conv1: 32->32 k5 p1: 21 -> 19 -> pool 9
// conv2: 32->64 k4 p1: 9  -> 8  -> pool 4
// conv3: 64->64 k3 p0: 4  -> 2          -> feat [80,512]
// fc1: 1024->256, fc2: 512->128, fc3: 256->6 (per-agent, mean-comm concat)

#define NN 80

typedef unsigned long long ull;

__device__ __forceinline__ ull pack2(float lo, float hi) {
    ull r; asm("mov.b64 %0, {%1, %2};" : "=l"(r) : "f"(lo), "f"(hi)); return r;
}
__device__ __forceinline__ void fma2(ull& d, ull a, ull b) {
    asm("fma.rn.f32x2 %0, %1, %2, %0;" : "+l"(d) : "l"(a), "l"(b));
}
__device__ __forceinline__ float2 unpack2(ull v) {
    float2 f; asm("mov.b64 {%0, %1}, %2;" : "=f"(f.x), "=f"(f.y) : "l"(v)); return f;
}

__device__ float g_buf0[80u * 32u * 21u * 21u * 21u];   // 94.8 MB
__device__ float g_buf1[80u * 32u * 9u * 9u * 9u];
__device__ float g_buf2[80u * 64u * 4u * 4u * 4u];
__device__ float g_feat[80u * 512u];
__device__ float g_mean1[16u * 512u];
__device__ float g_fc1[80u * 256u];
__device__ float g_mean2[16u * 256u];
__device__ float g_fc2[80u * 128u];
__device__ float g_mean3[16u * 128u];

// ---------------- conv0: 4->32, k5, pad1, fused pool2 ----------------
// f32x2 over CHANNEL PAIR, smem-staged padded input slices.
// grid (21 pz, 16 cg, 80 n), block (7 tx, 21 py)
__global__ __launch_bounds__(147, 3)
void conv0_kernel(const float* __restrict__ x,
                  const float* __restrict__ w,
                  const float* __restrict__ bias,
                  const float* __restrict__ prelu,
                  float* __restrict__ out) {
    const int pz = blockIdx.x, cg = blockIdx.y, n = blockIdx.z;
    const int tx = threadIdx.x, py = threadIdx.y;
    __shared__ __align__(16) ull ws[4 * 5 * 5 * 6];        // channel pairs, 4.8KB
    __shared__ __align__(16) float slice[4][47 * 48];      // padded (y:-1..45, x:-1..46), 36.1KB
    __shared__ float sb[2];
    __shared__ float sa;
    const int tid = py * 7 + tx;
    for (int i = tid; i < 500; i += 147) {
        const int ic = i / 125, rr = i % 125;
        const int kz = rr / 25, ky = (rr / 5) % 5, kx = rr % 5;
        const float w0 = w[(cg * 2 + 0) * 500 + i] * (1.0f / 255.0f);
        const float w1 = w[(cg * 2 + 1) * 500 + i] * (1.0f / 255.0f);
        ws[((ic * 5 + kz) * 5 + ky) * 6 + kx] = pack2(w0, w1);
    }
    if (tid < 2) sb[tid] = bias[cg * 2 + tid];
    if (tid == 0) sa = prelu[0];

    ull acc[3][2][2][2] = {};  // [pxl][ox][oz][oy], f32x2 over channel pair

    for (int zin = 0; zin < 6; zin++) {
        const int z = 2 * pz - 1 + zin;
        __syncthreads();
        // stage z-slice for all 4 ic, zero-padded
        for (int e = tid; e < 4 * 47 * 48; e += 147) {
            const int ic = e / 2256, r = e % 2256;
            const int yy = r / 48, xx = r % 48;
            const int y = yy - 1, xg = xx - 1;
            float v = 0.0f;
            if ((unsigned)z < 45u && (unsigned)y < 45u && (unsigned)xg < 45u)
                v = x[((size_t)(n * 4 + ic)) * (45 * 45 * 45) + (z * 45 + y) * 45 + xg];
            slice[ic][r] = v;
        }
        __syncthreads();

        const bool oz0 = (zin <= 4), oz1 = (zin >= 1);
        for (int ic = 0; ic < 4; ic++) {
            const float* sl = slice[ic];
#pragma unroll
            for (int yin = 0; yin < 6; yin++) {
                const int yy = 2 * py + yin;
                const float2* rp = (const float2*)(sl + yy * 48 + 6 * tx);
                float2 in2[5];
#pragma unroll
                for (int j = 0; j < 5; j++) in2[j] = rp[j];
                ull p[10];
#pragma unroll
                for (int j = 0; j < 5; j++) {
                    p[2 * j + 0] = pack2(in2[j].x, in2[j].x);
                    p[2 * j + 1] = pack2(in2[j].y, in2[j].y);
                }
                const bool oy0 = (yin <= 4), oy1 = (yin >= 1);
#pragma unroll
                for (int oz = 0; oz < 2; oz++) {
                    if (oz ? !oz1 : !oz0) continue;
                    const int kz = zin - oz;
#pragma unroll
                    for (int oy = 0; oy < 2; oy++) {
                        if (oy ? !oy1 : !oy0) continue;
                        const int ky = yin - oy;
                        const ull* wr = &ws[((ic * 5 + kz) * 5 + ky) * 6];
                        const ulonglong2 wab = *(const ulonglong2*)wr;
                        const ulonglong2 wcd = *(const ulonglong2*)(wr + 2);
                        const ull W4 = wr[4];
#pragma unroll
                        for (int pxl = 0; pxl < 3; pxl++) {
#pragma unroll
                            for (int ox = 0; ox < 2; ox++) {
                                ull& A = acc[pxl][ox][oz][oy];
                                const int b = 2 * pxl + ox;
                                fma2(A, wab.x, p[b + 0]);
                                fma2(A, wab.y, p[b + 1]);
                                fma2(A, wcd.x, p[b + 2]);
                                fma2(A, wcd.y, p[b + 3]);
                                fma2(A, W4,    p[b + 4]);
                            }
                        }
                    }
                }
            }
        }
    }
#pragma unroll
    for (int pxl = 0; pxl < 3; pxl++) {
        float m0 = -CUDART_INF_F, m1 = -CUDART_INF_F;
#pragma unroll
        for (int ox = 0; ox < 2; ox++)
#pragma unroll
            for (int oz = 0; oz < 2; oz++)
#pragma unroll
                for (int oy = 0; oy < 2; oy++) {
                    const float2 v = unpack2(acc[pxl][ox][oz][oy]);
                    m0 = fmaxf(m0, v.x);
                    m1 = fmaxf(m1, v.y);
                }
        m0 += sb[0]; m1 += sb[1];
        const float v0 = (m0 >= 0.0f) ? m0 : sa * m0;
        const float v1 = (m1 >= 0.0f) ? m1 : sa * m1;
        const int px = 3 * tx + pxl;
        out[(((size_t)(n * 32 + cg * 2 + 0) * 21 + pz) * 21 + py) * 21 + px] = v0;
        out[(((size_t)(n * 32 + cg * 2 + 1) * 21 + pz) * 21 + py) * 21 + px] = v1;
    }
}

// ---------------- conv1: 32->32, k5, pad1, fused pool2 ----------------
// f32x2 over CHANNEL PAIR, smem-staged padded per-ic input volume (dynamic smem).
// grid (16 cg, 80 n), block (3 tx, 9 py, 9 pz)
// dynamic smem: ws (38400B) + slab 23x23x24 floats (50784B) = 89184B
#define CONV1_SMEM (38400 + 50784)
__global__ __launch_bounds__(243, 2)
void conv1_kernel(const float* __restrict__ x,
                  const float* __restrict__ w,
                  const float* __restrict__ bias,
                  const float* __restrict__ prelu,
                  float* __restrict__ out) {
    extern __shared__ __align__(16) char dynsmem[];
    ull* ws = (ull*)dynsmem;                       // [32][5][5][6] channel pairs
    float* slab = (float*)(dynsmem + 38400);       // [23 z][23 y][24 x], padded
    __shared__ float sb[2];
    __shared__ float sa;

    const int cg = blockIdx.x, n = blockIdx.y;
    const int tx = threadIdx.x, py = threadIdx.y, pz = threadIdx.z;
    const int tid = (pz * 9 + py) * 3 + tx;
    for (int i = tid; i < 4000; i += 243) {
        const int ic = i / 125, rr = i % 125;
        const int kz = rr / 25, ky = (rr / 5) % 5, kx = rr % 5;
        const float w0 = w[(cg * 2 + 0) * 4000 + i];
        const float w1 = w[(cg * 2 + 1) * 4000 + i];
        ws[((ic * 5 + kz) * 5 + ky) * 6 + kx] = pack2(w0, w1);
    }
    if (tid < 2) sb[tid] = bias[cg * 2 + tid];
    if (tid == 0) sa = prelu[0];

    ull acc[3][2][2][2] = {};

    for (int ic = 0; ic < 32; ic++) {
        __syncthreads();
        // stage padded ic volume
        const float* xp = x + ((size_t)(n * 32 + ic)) * (21 * 21 * 21);
        for (int e = tid; e < 23 * 23 * 24; e += 243) {
            const int zz = e / 552, r = e % 552;
            const int yy = r / 24, xx = r % 24;
            const int z = zz - 1, y = yy - 1, xg = xx - 1;
            float v = 0.0f;
            if ((unsigned)z < 21u && (unsigned)y < 21u && (unsigned)xg < 21u)
                v = xp[(z * 21 + y) * 21 + xg];
            slab[e] = v;
        }
        __syncthreads();

#pragma unroll
        for (int zin = 0; zin < 6; zin++) {
            const int zz = 2 * pz + zin;
            const bool oz0 = (zin <= 4), oz1 = (zin >= 1);
#pragma unroll
            for (int yin = 0; yin < 6; yin++) {
                const int yy = 2 * py + yin;
                const float2* rp = (const float2*)(slab + (zz * 23 + yy) * 24 + 6 * tx);
                float2 in2[5];
#pragma unroll
                for (int j = 0; j < 5; j++) in2[j] = rp[j];
                ull p[10];
#pragma unroll
                for (int j = 0; j < 5; j++) {
                    p[2 * j + 0] = pack2(in2[j].x, in2[j].x);
                    p[2 * j + 1] = pack2(in2[j].y, in2[j].y);
                }
                const bool oy0 = (yin <= 4), oy1 = (yin >= 1);
#pragma unroll
                for (int oz = 0; oz < 2; oz++) {
                    if (oz ? !oz1 : !oz0) continue;
                    const int kz = zin - oz;
#pragma unroll
                    for (int oy = 0; oy < 2; oy++) {
                        if (oy ? !oy1 : !oy0) continue;
                        const int ky = yin - oy;
                        const ull* wr = &ws[((ic * 5 + kz) * 5 + ky) * 6];
                        const ulonglong2 wab = *(const ulonglong2*)wr;
                        const ulonglong2 wcd = *(const ulonglong2*)(wr + 2);
                        const ull W4 = wr[4];
#pragma unroll
                        for (int pxl = 0; pxl < 3; pxl++) {
#pragma unroll
                            for (int ox = 0; ox < 2; ox++) {
                                ull& A = acc[pxl][ox][oz][oy];
                                const int b = 2 * pxl + ox;
                                fma2(A, wab.x, p[b + 0]);
                                fma2(A, wab.y, p[b + 1]);
                                fma2(A, wcd.x, p[b + 2]);
                                fma2(A, wcd.y, p[b + 3]);
                                fma2(A, W4,    p[b + 4]);
                            }
                        }
                    }
                }
            }
        }
    }
#pragma unroll
    for (int pxl = 0; pxl < 3; pxl++) {
        float m0 = -CUDART_INF_F, m1 = -CUDART_INF_F;
#pragma unroll
        for (int ox = 0; ox < 2; ox++)
#pragma unroll
            for (int oz = 0; oz < 2; oz++)
#pragma unroll
                for (int oy = 0; oy < 2; oy++) {
                    const float2 v = unpack2(acc[pxl][ox][oz][oy]);
                    m0 = fmaxf(m0, v.x);
                    m1 = fmaxf(m1, v.y);
                }
        m0 += sb[0]; m1 += sb[1];
        const float v0 = (m0 >= 0.0f) ? m0 : sa * m0;
        const float v1 = (m1 >= 0.0f) ? m1 : sa * m1;
        const int px = 3 * tx + pxl;
        out[(((size_t)(n * 32 + cg * 2 + 0) * 9 + pz) * 9 + py) * 9 + px] = v0;
        out[(((size_t)(n * 32 + cg * 2 + 1) * 9 + pz) * 9 + py) * 9 + px] = v1;
    }
}

// ---------------- conv2: 32->64, k4, pad1, fused pool2, f32x2 over ox ----------------
// grid (16 cgroup, 80 n), block (4 py, 4 pz, 4 c4)
__global__ void conv2_kernel(const float* __restrict__ x,
                             const float* __restrict__ w,
                             const float* __restrict__ bias,
                             const float* __restrict__ prelu,
                             float* __restrict__ out) {
    const int bx = blockIdx.x, n = blockIdx.y;
    const int py = threadIdx.x, pz = threadIdx.y, c4 = threadIdx.z;
    __shared__ __align__(16) float ws[4 * 2048];  // [c4][ic][kz][ky][kx], 32KB
    __shared__ float sb[4];
    __shared__ float sa;
    const int tid = (c4 * 4 + pz) * 4 + py;
    for (int i = tid; i < 8192; i += 64) ws[i] = w[(size_t)bx * 8192 + i];
    if (tid < 4) sb[tid] = bias[bx * 4 + tid];
    if (tid == 0) sa = prelu[0];
    __syncthreads();

    ull acc[4][2][2] = {};  // [px][oz][oy], f32x2 over ox

    for (int ic = 0; ic < 32; ic++) {
        const float* xp = x + ((size_t)(n * 32 + ic)) * (9 * 9 * 9);
#pragma unroll
        for (int zin = 0; zin < 5; zin++) {
            const int z = 2 * pz - 1 + zin;
            if ((unsigned)z >= 9u) continue;
            const bool oz0 = (zin <= 3), oz1 = (zin >= 1);
#pragma unroll
            for (int yin = 0; yin < 5; yin++) {
                const int y = 2 * py - 1 + yin;
                if ((unsigned)y >= 9u) continue;
                const float* row = xp + (z * 9 + y) * 9;
                float in[11];
#pragma unroll
                for (int i = 0; i < 11; i++) {
                    const int xx = i - 1;
                    in[i] = ((unsigned)xx < 9u) ? __ldg(row + xx) : 0.0f;
                }
                ull p[10];
#pragma unroll
                for (int i = 0; i < 10; i++) p[i] = pack2(in[i], in[i + 1]);
                const bool oy0 = (yin <= 3), oy1 = (yin >= 1);
#pragma unroll
                for (int oz = 0; oz < 2; oz++) {
                    if (oz ? !oz1 : !oz0) continue;
                    const int kz = zin - oz;
#pragma unroll
                    for (int oy = 0; oy < 2; oy++) {
                        if (oy ? !oy1 : !oy0) continue;
                        const int ky = yin - oy;
                        const float* wr = &ws[((c4 * 32 + ic) * 16 + kz * 4 + ky) * 4];
                        const float4 w4 = *(const float4*)wr;
                        const ull W0 = pack2(w4.x, w4.x), W1 = pack2(w4.y, w4.y),
                                  W2 = pack2(w4.z, w4.z), W3 = pack2(w4.w, w4.w);
#pragma unroll
                        for (int px = 0; px < 4; px++) {
                            ull& A = acc[px][oz][oy];
                            fma2(A, W0, p[2 * px + 0]);
                            fma2(A, W1, p[2 * px + 1]);
                            fma2(A, W2, p[2 * px + 2]);
                            fma2(A, W3, p[2 * px + 3]);
                        }
                    }
                }
            }
        }
    }
    const float b = sb[c4];
#pragma unroll
    for (int px = 0; px < 4; px++) {
        float m = -CUDART_INF_F;
#pragma unroll
        for (int oz = 0; oz < 2; oz++)
#pragma unroll
            for (int oy = 0; oy < 2; oy++) {
                const float2 v = unpack2(acc[px][oz][oy]);
                m = fmaxf(m, fmaxf(v.x, v.y));
            }
        m += b;
        const float v = (m >= 0.0f) ? m : sa * m;
        out[(((size_t)(n * 64 + bx * 4 + c4) * 4 + pz) * 4 + py) * 4 + px] = v;
    }
}

// ---------------- conv3: 64->64, k3, pad0, + reshape to feat ----------------
__global__ void conv3_kernel(const float* __restrict__ x,
                             const float* __restrict__ w,
                             const float* __restrict__ bias,
                             const float* __restrict__ prelu,
                             float* __restrict__ feat) {
    const int n = blockIdx.x;
    const int tid = threadIdx.x;
    __shared__ float sin[64 * 64];  // [ic][z*16+y*4+x]
    for (int i = tid; i < 4096; i += 512) sin[i] = x[(size_t)n * 4096 + i];
    __syncthreads();

    const int c = tid >> 3, s = tid & 7;
    const int oz = s >> 2, oy = (s >> 1) & 1, ox = s & 1;
    float acc = bias[c];
    const float* wc = w + (size_t)c * 64 * 27;
    for (int ic = 0; ic < 64; ic++) {
        const float* si = sin + ic * 64;
        const float* wi = wc + ic * 27;
#pragma unroll
        for (int kz = 0; kz < 3; kz++)
#pragma unroll
            for (int ky = 0; ky < 3; ky++)
#pragma unroll
                for (int kx = 0; kx < 3; kx++)
                    acc = fmaf(__ldg(wi + (kz * 3 + ky) * 3 + kx),
                               si[(oz + kz) * 16 + (oy + ky) * 4 + (ox + kx)], acc);
    }
    const float a = prelu[0];
    const float v = (acc >= 0.0f) ? acc : a * acc;
    feat[(size_t)n * 512 + c * 8 + s] = v;
}

// ---------------- mean over agents ----------------
__global__ void mean_kernel(const float* __restrict__ feat, float* __restrict__ mean, int D) {
    const int b = blockIdx.x, i = threadIdx.x;
    float s = 0.0f;
    for (int a = 0; a < 5; a++) s += feat[((size_t)(b * 5 + a)) * D + i];
    mean[(size_t)b * D + i] = s * (1.0f / 5.0f);
}

// ---------------- comm fc (+optional prelu) ----------------
__global__ void commfc_kernel(const float* __restrict__ feat,
                              const float* __restrict__ mean,
                              const float* __restrict__ w,
                              const float* __restrict__ bias,
                              const float* __restrict__ prelu,
                              float* __restrict__ out, int D, int O) {
    const int bx = blockIdx.x;
    const int b = bx / 5, a = bx % 5;
    const int o = threadIdx.x;
    if (o >= O) return;
    const float* fp = feat + (size_t)bx * D;
    const float* mp = mean + (size_t)b * D;
    const float* wp = w + ((size_t)a * O + o) * (2 * D);
    float acc = bias[a * O + o];
    for (int i = 0; i < D; i++) {
        acc = fmaf(fp[i], __ldg(wp + i), acc);
        acc = fmaf(mp[i], __ldg(wp + D + i), acc);
    }
    if (prelu) {
        const float al = prelu[0];
        acc = (acc >= 0.0f) ? acc : al * acc;
    }
    out[(size_t)bx * O + o] = acc;
}

extern "C" void kernel_launch(void* const* d_in, const int* in_sizes, int n_in,
                              void* d_out, int out_size) {
    const float* x        = (const float*)d_in[0];
    const float* conv0_w  = (const float*)d_in[1];
    const float* conv0_b  = (const float*)d_in[2];
    const float* prelu0   = (const float*)d_in[3];
    const float* conv1_w  = (const float*)d_in[4];
    const float* conv1_b  = (const float*)d_in[5];
    const float* prelu1   = (const float*)d_in[6];
    const float* conv2_w  = (const float*)d_in[7];
    const float* conv2_b  = (const float*)d_in[8];
    const float* prelu2   = (const float*)d_in[9];
    const float* conv3_w  = (const float*)d_in[10];
    const float* conv3_b  = (const float*)d_in[11];
    const float* prelu3   = (const float*)d_in[12];
    const float* fc1_w    = (const float*)d_in[13];
    const float* fc1_b    = (const float*)d_in[14];
    const float* prelu4   = (const float*)d_in[15];
    const float* fc2_w    = (const float*)d_in[16];
    const float* fc2_b    = (const float*)d_in[17];
    const float* prelu5   = (const float*)d_in[18];
    const float* fc3_w    = (const float*)d_in[19];
    const float* fc3_b    = (const float*)d_in[20];
    float* out = (float*)d_out;

    float *buf0, *buf1, *buf2, *feat, *mean1, *fc1, *mean2, *fc2, *mean3;
    cudaGetSymbolAddress((void**)&buf0,  g_buf0);
    cudaGetSymbolAddress((void**)&buf1,  g_buf1);
    cudaGetSymbolAddress((void**)&buf2,  g_buf2);
    cudaGetSymbolAddress((void**)&feat,  g_feat);
    cudaGetSymbolAddress((void**)&mean1, g_mean1);
    cudaGetSymbolAddress((void**)&fc1,   g_fc1);
    cudaGetSymbolAddress((void**)&mean2, g_mean2);
    cudaGetSymbolAddress((void**)&fc2,   g_fc2);
    cudaGetSymbolAddress((void**)&mean3, g_mean3);

    cudaFuncSetAttribute(conv1_kernel, cudaFuncAttributeMaxDynamicSharedMemorySize, CONV1_SMEM);

    conv0_kernel<<<dim3(21, 16, NN), dim3(7, 21)>>>(x, conv0_w, conv0_b, prelu0, buf0);
    conv1_kernel<<<dim3(16, NN), dim3(3, 9, 9), CONV1_SMEM>>>(buf0, conv1_w, conv1_b, prelu1, buf1);
    conv2_kernel<<<dim3(16, NN), dim3(4, 4, 4)>>>(buf1, conv2_w, conv2_b, prelu2, buf2);
    conv3_kernel<<<NN, 512>>>(buf2, conv3_w, conv3_b, prelu3, feat);

    mean_kernel<<<16, 512>>>(feat, mean1, 512);
    commfc_kernel<<<NN, 256>>>(feat, mean1, fc1_w, fc1_b, prelu4, fc1, 512, 256);
    mean_kernel<<<16, 256>>>(fc1, mean2, 256);
    commfc_kernel<<<NN, 128>>>(fc1, mean2, fc2_w, fc2_b, prelu5, fc2, 256, 128);
    mean_kernel<<<16, 128>>>(fc2, mean3, 128);
    commfc_kernel<<<NN, 32>>>(fc2, mean3, fc3_w, fc3_b, nullptr, out, 128, 6);
}

// round 8
// speedup vs baseline: 1.4570x; 1.4570x over previous
#include <cuda_runtime.h>
#include <cuda_bf16.h>
#include <math_constants.h>

// ---------------- shapes ----------------
// B=16, A=5 -> N = 80 folded batch
// conv0: 4->32 k5 p1 : 45 -> 43 -> pool 21
// conv1: 32->32 k5 p1: 21 -> 19 -> pool 9
// conv2: 32->64 k4 p1: 9  -> 8  -> pool 4
// conv3: 64->64 k3 p0: 4  -> 2          -> feat [80,512]
// fc1: 1024->256, fc2: 512->128, fc3: 256->6 (per-agent, mean-comm concat)
//
// Strategy: zero-padded GMEM intermediates (halos never written; __device__
// globals are zero-initialized at load) -> all conv input loads are
// unconditional aligned LDG.64, no bounds selects, no smem staging.

#define NN 80

typedef unsigned long long ull;

__device__ __forceinline__ ull pack2(float lo, float hi) {
    ull r; asm("mov.b64 %0, {%1, %2};" : "=l"(r) : "f"(lo), "f"(hi)); return r;
}
__device__ __forceinline__ void fma2(ull& d, ull a, ull b) {
    asm("fma.rn.f32x2 %0, %1, %2, %0;" : "+l"(d) : "l"(a), "l"(b));
}
__device__ __forceinline__ float2 unpack2(ull v) {
    float2 f; asm("mov.b64 {%0, %1}, %2;" : "=f"(f.x), "=f"(f.y) : "l"(v)); return f;
}

// padded tensors (halo = zero, never written)
__device__ float g_xpad[80u * 4u * 47u * 47u * 48u];    // 135.7 MB, [n][ic][47][47][48]
__device__ float g_buf0[80u * 32u * 23u * 23u * 24u];   // 130 MB,   [n][c][23][23][24]
__device__ float g_buf1[80u * 32u * 11u * 11u * 12u];   // 14.9 MB,  [n][c][11][11][12]
__device__ float g_buf2[80u * 64u * 4u * 4u * 4u];
__device__ float g_feat[80u * 512u];
__device__ float g_mean1[16u * 512u];
__device__ float g_fc1[80u * 256u];
__device__ float g_mean2[16u * 256u];
__device__ float g_fc2[80u * 128u];
__device__ float g_mean3[16u * 128u];

// ---------------- pad x into g_xpad interior ----------------
__global__ void pad_x_kernel(const float* __restrict__ x, float* __restrict__ xp) {
    const size_t i = (size_t)blockIdx.x * blockDim.x + threadIdx.x;
    const size_t total = 80u * 4u * 45u * 45u * 45u;
    if (i >= total) return;
    const int xc = (int)(i % 45);
    size_t t = i / 45;
    const int y = (int)(t % 45); t /= 45;
    const int z = (int)(t % 45);
    const int nc = (int)(t / 45);
    xp[(((size_t)nc * 47 + (z + 1)) * 47 + (y + 1)) * 48 + (xc + 1)] = x[i];
}

// ---------------- conv0: 4->32, k5, pad1, fused pool2 ----------------
// f32x2 over CHANNEL PAIR, padded gmem input -> unconditional LDG.64.
// grid (21 pz, 16 cg, 80 n), block (7 tx, 21 py)
__global__ void conv0_kernel(const float* __restrict__ xp,
                             const float* __restrict__ w,
                             const float* __restrict__ bias,
                             const float* __restrict__ prelu,
                             float* __restrict__ out) {
    const int pz = blockIdx.x, cg = blockIdx.y, n = blockIdx.z;
    const int tx = threadIdx.x, py = threadIdx.y;
    __shared__ __align__(16) ull ws[4 * 5 * 5 * 6];  // channel pairs, kx padded->6
    __shared__ float sb[2];
    __shared__ float sa;
    const int tid = py * 7 + tx;
    for (int i = tid; i < 500; i += 147) {
        const int ic = i / 125, rr = i % 125;
        const int kz = rr / 25, ky = (rr / 5) % 5, kx = rr % 5;
        const float w0 = w[(cg * 2 + 0) * 500 + i] * (1.0f / 255.0f);
        const float w1 = w[(cg * 2 + 1) * 500 + i] * (1.0f / 255.0f);
        ws[((ic * 5 + kz) * 5 + ky) * 6 + kx] = pack2(w0, w1);
    }
    if (tid < 2) sb[tid] = bias[cg * 2 + tid];
    if (tid == 0) sa = prelu[0];
    __syncthreads();

    ull acc[3][2][2][2] = {};  // [pxl][ox][oz][oy], f32x2 over channel pair

    for (int ic = 0; ic < 4; ic++) {
        const float* base = xp + ((size_t)(n * 4 + ic)) * (47 * 47 * 48);
        for (int zin = 0; zin < 6; zin++) {
            const int zp = 2 * pz + zin;  // padded z, always in range
            const bool oz0 = (zin <= 4), oz1 = (zin >= 1);
#pragma unroll
            for (int yin = 0; yin < 6; yin++) {
                const int yp = 2 * py + yin;
                const float2* rp = (const float2*)(base + ((size_t)zp * 47 + yp) * 48 + 6 * tx);
                float2 v[5];
#pragma unroll
                for (int j = 0; j < 5; j++) v[j] = __ldg(rp + j);
                ull p[10];
#pragma unroll
                for (int j = 0; j < 5; j++) {
                    p[2 * j + 0] = pack2(v[j].x, v[j].x);
                    p[2 * j + 1] = pack2(v[j].y, v[j].y);
                }
                const bool oy0 = (yin <= 4), oy1 = (yin >= 1);
#pragma unroll
                for (int oz = 0; oz < 2; oz++) {
                    if (oz ? !oz1 : !oz0) continue;
                    const int kz = zin - oz;
#pragma unroll
                    for (int oy = 0; oy < 2; oy++) {
                        if (oy ? !oy1 : !oy0) continue;
                        const int ky = yin - oy;
                        const ull* wr = &ws[((ic * 5 + kz) * 5 + ky) * 6];
                        const ulonglong2 wab = *(const ulonglong2*)wr;
                        const ulonglong2 wcd = *(const ulonglong2*)(wr + 2);
                        const ull W4 = wr[4];
#pragma unroll
                        for (int pxl = 0; pxl < 3; pxl++) {
#pragma unroll
                            for (int ox = 0; ox < 2; ox++) {
                                ull& A = acc[pxl][ox][oz][oy];
                                const int b = 2 * pxl + ox;
                                fma2(A, wab.x, p[b + 0]);
                                fma2(A, wab.y, p[b + 1]);
                                fma2(A, wcd.x, p[b + 2]);
                                fma2(A, wcd.y, p[b + 3]);
                                fma2(A, W4,    p[b + 4]);
                            }
                        }
                    }
                }
            }
        }
    }
#pragma unroll
    for (int pxl = 0; pxl < 3; pxl++) {
        float m0 = -CUDART_INF_F, m1 = -CUDART_INF_F;
#pragma unroll
        for (int ox = 0; ox < 2; ox++)
#pragma unroll
            for (int oz = 0; oz < 2; oz++)
#pragma unroll
                for (int oy = 0; oy < 2; oy++) {
                    const float2 v = unpack2(acc[pxl][ox][oz][oy]);
                    m0 = fmaxf(m0, v.x);
                    m1 = fmaxf(m1, v.y);
                }
        m0 += sb[0]; m1 += sb[1];
        const float v0 = (m0 >= 0.0f) ? m0 : sa * m0;
        const float v1 = (m1 >= 0.0f) ? m1 : sa * m1;
        const int px = 3 * tx + pxl;
        // write padded buf0 interior
        out[(((size_t)(n * 32 + cg * 2 + 0) * 23 + pz + 1) * 23 + py + 1) * 24 + px + 1] = v0;
        out[(((size_t)(n * 32 + cg * 2 + 1) * 23 + pz + 1) * 23 + py + 1) * 24 + px + 1] = v1;
    }
}

// ---------------- conv1: 32->32, k5, pad1, fused pool2 ----------------
// f32x2 over CHANNEL PAIR, padded gmem input -> unconditional LDG.64.
// grid (16 cg, 80 n), block (3 tx, 9 py, 9 pz)
__global__ void conv1_kernel(const float* __restrict__ xpad,
                             const float* __restrict__ w,
                             const float* __restrict__ bias,
                             const float* __restrict__ prelu,
                             float* __restrict__ out) {
    const int cg = blockIdx.x, n = blockIdx.y;
    const int tx = threadIdx.x, py = threadIdx.y, pz = threadIdx.z;
    __shared__ __align__(16) ull ws[32 * 5 * 5 * 6];  // 38.4KB channel pairs
    __shared__ float sb[2];
    __shared__ float sa;
    const int tid = (pz * 9 + py) * 3 + tx;
    for (int i = tid; i < 4000; i += 243) {
        const int ic = i / 125, rr = i % 125;
        const int kz = rr / 25, ky = (rr / 5) % 5, kx = rr % 5;
        const float w0 = w[(cg * 2 + 0) * 4000 + i];
        const float w1 = w[(cg * 2 + 1) * 4000 + i];
        ws[((ic * 5 + kz) * 5 + ky) * 6 + kx] = pack2(w0, w1);
    }
    if (tid < 2) sb[tid] = bias[cg * 2 + tid];
    if (tid == 0) sa = prelu[0];
    __syncthreads();

    ull acc[3][2][2][2] = {};

    for (int ic = 0; ic < 32; ic++) {
        const float* base = xpad + ((size_t)(n * 32 + ic)) * (23 * 23 * 24);
#pragma unroll 2
        for (int zin = 0; zin < 6; zin++) {
            const int zp = 2 * pz + zin;
            const bool oz0 = (zin <= 4), oz1 = (zin >= 1);
#pragma unroll
            for (int yin = 0; yin < 6; yin++) {
                const int yp = 2 * py + yin;
                const float2* rp = (const float2*)(base + ((size_t)zp * 23 + yp) * 24 + 6 * tx);
                float2 v[5];
#pragma unroll
                for (int j = 0; j < 5; j++) v[j] = __ldg(rp + j);
                ull p[10];
#pragma unroll
                for (int j = 0; j < 5; j++) {
                    p[2 * j + 0] = pack2(v[j].x, v[j].x);
                    p[2 * j + 1] = pack2(v[j].y, v[j].y);
                }
                const bool oy0 = (yin <= 4), oy1 = (yin >= 1);
#pragma unroll
                for (int oz = 0; oz < 2; oz++) {
                    if (oz ? !oz1 : !oz0) continue;
                    const int kz = zin - oz;
#pragma unroll
                    for (int oy = 0; oy < 2; oy++) {
                        if (oy ? !oy1 : !oy0) continue;
                        const int ky = yin - oy;
                        const ull* wr = &ws[((ic * 5 + kz) * 5 + ky) * 6];
                        const ulonglong2 wab = *(const ulonglong2*)wr;
                        const ulonglong2 wcd = *(const ulonglong2*)(wr + 2);
                        const ull W4 = wr[4];
#pragma unroll
                        for (int pxl = 0; pxl < 3; pxl++) {
#pragma unroll
                            for (int ox = 0; ox < 2; ox++) {
                                ull& A = acc[pxl][ox][oz][oy];
                                const int b = 2 * pxl + ox;
                                fma2(A, wab.x, p[b + 0]);
                                fma2(A, wab.y, p[b + 1]);
                                fma2(A, wcd.x, p[b + 2]);
                                fma2(A, wcd.y, p[b + 3]);
                                fma2(A, W4,    p[b + 4]);
                            }
                        }
                    }
                }
            }
        }
    }
#pragma unroll
    for (int pxl = 0; pxl < 3; pxl++) {
        float m0 = -CUDART_INF_F, m1 = -CUDART_INF_F;
#pragma unroll
        for (int ox = 0; ox < 2; ox++)
#pragma unroll
            for (int oz = 0; oz < 2; oz++)
#pragma unroll
                for (int oy = 0; oy < 2; oy++) {
                    const float2 v = unpack2(acc[pxl][ox][oz][oy]);
                    m0 = fmaxf(m0, v.x);
                    m1 = fmaxf(m1, v.y);
                }
        m0 += sb[0]; m1 += sb[1];
        const float v0 = (m0 >= 0.0f) ? m0 : sa * m0;
        const float v1 = (m1 >= 0.0f) ? m1 : sa * m1;
        const int px = 3 * tx + pxl;
        // write padded buf1 interior
        out[(((size_t)(n * 32 + cg * 2 + 0) * 11 + pz + 1) * 11 + py + 1) * 12 + px + 1] = v0;
        out[(((size_t)(n * 32 + cg * 2 + 1) * 11 + pz + 1) * 11 + py + 1) * 12 + px + 1] = v1;
    }
}

// ---------------- conv2: 32->64, k4, pad1, fused pool2, f32x2 over ox ----------------
// padded gmem input -> unconditional loads. grid (16 cgroup, 80 n), block (4,4,4)
__global__ void conv2_kernel(const float* __restrict__ xpad,
                             const float* __restrict__ w,
                             const float* __restrict__ bias,
                             const float* __restrict__ prelu,
                             float* __restrict__ out) {
    const int bx = blockIdx.x, n = blockIdx.y;
    const int py = threadIdx.x, pz = threadIdx.y, c4 = threadIdx.z;
    __shared__ __align__(16) float ws[4 * 2048];  // [c4][ic][kz][ky][kx], 32KB
    __shared__ float sb[4];
    __shared__ float sa;
    const int tid = (c4 * 4 + pz) * 4 + py;
    for (int i = tid; i < 8192; i += 64) ws[i] = w[(size_t)bx * 8192 + i];
    if (tid < 4) sb[tid] = bias[bx * 4 + tid];
    if (tid == 0) sa = prelu[0];
    __syncthreads();

    ull acc[4][2][2] = {};  // [px][oz][oy], f32x2 over ox

    for (int ic = 0; ic < 32; ic++) {
        const float* base = xpad + ((size_t)(n * 32 + ic)) * (11 * 11 * 12);
#pragma unroll
        for (int zin = 0; zin < 5; zin++) {
            const int zp = 2 * pz + zin;
            const bool oz0 = (zin <= 3), oz1 = (zin >= 1);
#pragma unroll
            for (int yin = 0; yin < 5; yin++) {
                const int yp = 2 * py + yin;
                const float* row = base + ((size_t)zp * 11 + yp) * 12;
                const float2* rp = (const float2*)row;
                float2 v[5];
#pragma unroll
                for (int j = 0; j < 5; j++) v[j] = __ldg(rp + j);
                const float last = __ldg(row + 10);
                float in[11];
#pragma unroll
                for (int j = 0; j < 5; j++) { in[2 * j] = v[j].x; in[2 * j + 1] = v[j].y; }
                in[10] = last;
                ull p[10];
#pragma unroll
                for (int i = 0; i < 10; i++) p[i] = pack2(in[i], in[i + 1]);
                const bool oy0 = (yin <= 3), oy1 = (yin >= 1);
#pragma unroll
                for (int oz = 0; oz < 2; oz++) {
                    if (oz ? !oz1 : !oz0) continue;
                    const int kz = zin - oz;
#pragma unroll
                    for (int oy = 0; oy < 2; oy++) {
                        if (oy ? !oy1 : !oy0) continue;
                        const int ky = yin - oy;
                        const float* wr = &ws[((c4 * 32 + ic) * 16 + kz * 4 + ky) * 4];
                        const float4 w4 = *(const float4*)wr;
                        const ull W0 = pack2(w4.x, w4.x), W1 = pack2(w4.y, w4.y),
                                  W2 = pack2(w4.z, w4.z), W3 = pack2(w4.w, w4.w);
#pragma unroll
                        for (int px = 0; px < 4; px++) {
                            ull& A = acc[px][oz][oy];
                            fma2(A, W0, p[2 * px + 0]);
                            fma2(A, W1, p[2 * px + 1]);
                            fma2(A, W2, p[2 * px + 2]);
                            fma2(A, W3, p[2 * px + 3]);
                        }
                    }
                }
            }
        }
    }
    const float b = sb[c4];
#pragma unroll
    for (int px = 0; px < 4; px++) {
        float m = -CUDART_INF_F;
#pragma unroll
        for (int oz = 0; oz < 2; oz++)
#pragma unroll
            for (int oy = 0; oy < 2; oy++) {
                const float2 v = unpack2(acc[px][oz][oy]);
                m = fmaxf(m, fmaxf(v.x, v.y));
            }
        m += b;
        const float v = (m >= 0.0f) ? m : sa * m;
        out[(((size_t)(n * 64 + bx * 4 + c4) * 4 + pz) * 4 + py) * 4 + px] = v;
    }
}

// ---------------- conv3: 64->64, k3, pad0, + reshape to feat ----------------
__global__ void conv3_kernel(const float* __restrict__ x,
                             const float* __restrict__ w,
                             const float* __restrict__ bias,
                             const float* __restrict__ prelu,
                             float* __restrict__ feat) {
    const int n = blockIdx.x;
    const int tid = threadIdx.x;
    __shared__ float sin[64 * 64];  // [ic][z*16+y*4+x]
    for (int i = tid; i < 4096; i += 512) sin[i] = x[(size_t)n * 4096 + i];
    __syncthreads();

    const int c = tid >> 3, s = tid & 7;
    const int oz = s >> 2, oy = (s >> 1) & 1, ox = s & 1;
    float acc = bias[c];
    const float* wc = w + (size_t)c * 64 * 27;
    for (int ic = 0; ic < 64; ic++) {
        const float* si = sin + ic * 64;
        const float* wi = wc + ic * 27;
#pragma unroll
        for (int kz = 0; kz < 3; kz++)
#pragma unroll
            for (int ky = 0; ky < 3; ky++)
#pragma unroll
                for (int kx = 0; kx < 3; kx++)
                    acc = fmaf(__ldg(wi + (kz * 3 + ky) * 3 + kx),
                               si[(oz + kz) * 16 + (oy + ky) * 4 + (ox + kx)], acc);
    }
    const float a = prelu[0];
    const float v = (acc >= 0.0f) ? acc : a * acc;
    feat[(size_t)n * 512 + c * 8 + s] = v;
}

// ---------------- mean over agents ----------------
__global__ void mean_kernel(const float* __restrict__ feat, float* __restrict__ mean, int D) {
    const int b = blockIdx.x, i = threadIdx.x;
    float s = 0.0f;
    for (int a = 0; a < 5; a++) s += feat[((size_t)(b * 5 + a)) * D + i];
    mean[(size_t)b * D + i] = s * (1.0f / 5.0f);
}

// ---------------- comm fc (+optional prelu) ----------------
__global__ void commfc_kernel(const float* __restrict__ feat,
                              const float* __restrict__ mean,
                              const float* __restrict__ w,
                              const float* __restrict__ bias,
                              const float* __restrict__ prelu,
                              float* __restrict__ out, int D, int O) {
    const int bx = blockIdx.x;
    const int b = bx / 5, a = bx % 5;
    const int o = threadIdx.x;
    if (o >= O) return;
    const float* fp = feat + (size_t)bx * D;
    const float* mp = mean + (size_t)b * D;
    const float* wp = w + ((size_t)a * O + o) * (2 * D);
    float acc = bias[a * O + o];
    for (int i = 0; i < D; i++) {
        acc = fmaf(fp[i], __ldg(wp + i), acc);
        acc = fmaf(mp[i], __ldg(wp + D + i), acc);
    }
    if (prelu) {
        const float al = prelu[0];
        acc = (acc >= 0.0f) ? acc : al * acc;
    }
    out[(size_t)bx * O + o] = acc;
}

extern "C" void kernel_launch(void* const* d_in, const int* in_sizes, int n_in,
                              void* d_out, int out_size) {
    const float* x        = (const float*)d_in[0];
    const float* conv0_w  = (const float*)d_in[1];
    const float* conv0_b  = (const float*)d_in[2];
    const float* prelu0   = (const float*)d_in[3];
    const float* conv1_w  = (const float*)d_in[4];
    const float* conv1_b  = (const float*)d_in[5];
    const float* prelu1   = (const float*)d_in[6];
    const float* conv2_w  = (const float*)d_in[7];
    const float* conv2_b  = (const float*)d_in[8];
    const float* prelu2   = (const float*)d_in[9];
    const float* conv3_w  = (const float*)d_in[10];
    const float* conv3_b  = (const float*)d_in[11];
    const float* prelu3   = (const float*)d_in[12];
    const float* fc1_w    = (const float*)d_in[13];
    const float* fc1_b    = (const float*)d_in[14];
    const float* prelu4   = (const float*)d_in[15];
    const float* fc2_w    = (const float*)d_in[16];
    const float* fc2_b    = (const float*)d_in[17];
    const float* prelu5   = (const float*)d_in[18];
    const float* fc3_w    = (const float*)d_in[19];
    const float* fc3_b    = (const float*)d_in[20];
    float* out = (float*)d_out;

    float *xpad, *buf0, *buf1, *buf2, *feat, *mean1, *fc1, *mean2, *fc2, *mean3;
    cudaGetSymbolAddress((void**)&xpad,  g_xpad);
    cudaGetSymbolAddress((void**)&buf0,  g_buf0);
    cudaGetSymbolAddress((void**)&buf1,  g_buf1);
    cudaGetSymbolAddress((void**)&buf2,  g_buf2);
    cudaGetSymbolAddress((void**)&feat,  g_feat);
    cudaGetSymbolAddress((void**)&mean1, g_mean1);
    cudaGetSymbolAddress((void**)&fc1,   g_fc1);
    cudaGetSymbolAddress((void**)&mean2, g_mean2);
    cudaGetSymbolAddress((void**)&fc2,   g_fc2);
    cudaGetSymbolAddress((void**)&mean3, g_mean3);

    const size_t xtotal = 80u * 4u * 45u * 45u * 45u;
    pad_x_kernel<<<(unsigned)((xtotal + 255) / 256), 256>>>(x, xpad);

    conv0_kernel<<<dim3(21, 16, NN), dim3(7, 21)>>>(xpad, conv0_w, conv0_b, prelu0, buf0);
    conv1_kernel<<<dim3(16, NN), dim3(3, 9, 9)>>>(buf0, conv1_w, conv1_b, prelu1, buf1);
    conv2_kernel<<<dim3(16, NN), dim3(4, 4, 4)>>>(buf1, conv2_w, conv2_b, prelu2, buf2);
    conv3_kernel<<<NN, 512>>>(buf2, conv3_w, conv3_b, prelu3, feat);

    mean_kernel<<<16, 512>>>(feat, mean1, 512);
    commfc_kernel<<<NN, 256>>>(feat, mean1, fc1_w, fc1_b, prelu4, fc1, 512, 256);
    mean_kernel<<<16, 256>>>(fc1, mean2, 256);
    commfc_kernel<<<NN, 128>>>(fc1, mean2, fc2_w, fc2_b, prelu5, fc2, 256, 128);
    mean_kernel<<<16, 128>>>(fc2, mean3, 128);
    commfc_kernel<<<NN, 32>>>(fc2, mean3, fc3_w, fc3_b, nullptr, out, 128, 6);
}

// round 9
// speedup vs baseline: 1.5680x; 1.0762x over previous
#include <cuda_runtime.h>
#include <cuda_bf16.h>
#include <math_constants.h>

// ---------------- shapes ----------------
// B=16, A=5 -> N = 80 folded batch
// conv0: 4->32 k5 p1 : 45 -> 43 -> pool 21
// conv1: 32->32 k5 p1: 21 -> 19 -> pool 9
// conv2: 32->64 k4 p1: 9  -> 8  -> pool 4
// conv3: 64->64 k3 p0: 4  -> 2          -> feat [80,512]
// fc1: 1024->256, fc2: 512->128, fc3: 256->6 (per-agent, mean-comm concat)
//
// Zero-padded GMEM intermediates (halos never written; __device__ globals are
// zero-initialized) -> conv input loads are unconditional aligned LDG.64.

#define NN 80

typedef unsigned long long ull;

__device__ __forceinline__ ull pack2(float lo, float hi) {
    ull r; asm("mov.b64 %0, {%1, %2};" : "=l"(r) : "f"(lo), "f"(hi)); return r;
}
__device__ __forceinline__ void fma2(ull& d, ull a, ull b) {
    asm("fma.rn.f32x2 %0, %1, %2, %0;" : "+l"(d) : "l"(a), "l"(b));
}
__device__ __forceinline__ float2 unpack2(ull v) {
    float2 f; asm("mov.b64 {%0, %1}, %2;" : "=f"(f.x), "=f"(f.y) : "l"(v)); return f;
}

// padded tensors (halo = zero, never written)
__device__ float g_xpad[80u * 4u * 47u * 47u * 48u];    // 135.7 MB, [n][ic][47][47][48]
__device__ float g_buf0[80u * 32u * 23u * 23u * 24u];   // 130 MB,   [n][c][23][23][24]
__device__ float g_buf1[80u * 32u * 11u * 11u * 12u];   // 14.9 MB,  [n][c][11][11][12]
__device__ float g_buf2[80u * 64u * 4u * 4u * 4u];
__device__ float g_feat[80u * 512u];
__device__ float g_mean1[16u * 512u];
__device__ float g_fc1[80u * 256u];
__device__ float g_mean2[16u * 256u];
__device__ float g_fc2[80u * 128u];
__device__ float g_mean3[16u * 128u];

// ---------------- pad x into g_xpad interior ----------------
__global__ void pad_x_kernel(const float* __restrict__ x, float* __restrict__ xp) {
    const size_t i = (size_t)blockIdx.x * blockDim.x + threadIdx.x;
    const size_t total = 80u * 4u * 45u * 45u * 45u;
    if (i >= total) return;
    const int xc = (int)(i % 45);
    size_t t = i / 45;
    const int y = (int)(t % 45); t /= 45;
    const int z = (int)(t % 45);
    const int nc = (int)(t / 45);
    xp[(((size_t)nc * 47 + (z + 1)) * 47 + (y + 1)) * 48 + (xc + 1)] = x[i];
}

// ---------------- conv0: 4->32, k5, pad1, fused pool2 ----------------
// f32x2 over CHANNEL PAIR, padded gmem input -> unconditional LDG.64.
// grid (21 pz, 16 cg, 80 n), block (7 tx, 21 py)
__global__ void conv0_kernel(const float* __restrict__ xp,
                             const float* __restrict__ w,
                             const float* __restrict__ bias,
                             const float* __restrict__ prelu,
                             float* __restrict__ out) {
    const int pz = blockIdx.x, cg = blockIdx.y, n = blockIdx.z;
    const int tx = threadIdx.x, py = threadIdx.y;
    __shared__ __align__(16) ull ws[4 * 5 * 5 * 6];  // channel pairs, kx padded->6
    __shared__ float sb[2];
    __shared__ float sa;
    const int tid = py * 7 + tx;
    for (int i = tid; i < 500; i += 147) {
        const int ic = i / 125, rr = i % 125;
        const int kz = rr / 25, ky = (rr / 5) % 5, kx = rr % 5;
        const float w0 = w[(cg * 2 + 0) * 500 + i] * (1.0f / 255.0f);
        const float w1 = w[(cg * 2 + 1) * 500 + i] * (1.0f / 255.0f);
        ws[((ic * 5 + kz) * 5 + ky) * 6 + kx] = pack2(w0, w1);
    }
    if (tid < 2) sb[tid] = bias[cg * 2 + tid];
    if (tid == 0) sa = prelu[0];
    __syncthreads();

    ull acc[3][2][2][2] = {};  // [pxl][ox][oz][oy], f32x2 over channel pair

    for (int ic = 0; ic < 4; ic++) {
        const float* base = xp + ((size_t)(n * 4 + ic)) * (47 * 47 * 48);
        for (int zin = 0; zin < 6; zin++) {
            const int zp = 2 * pz + zin;  // padded z, always in range
            const bool oz0 = (zin <= 4), oz1 = (zin >= 1);
#pragma unroll
            for (int yin = 0; yin < 6; yin++) {
                const int yp = 2 * py + yin;
                const float2* rp = (const float2*)(base + ((size_t)zp * 47 + yp) * 48 + 6 * tx);
                float2 v[5];
#pragma unroll
                for (int j = 0; j < 5; j++) v[j] = __ldg(rp + j);
                ull p[10];
#pragma unroll
                for (int j = 0; j < 5; j++) {
                    p[2 * j + 0] = pack2(v[j].x, v[j].x);
                    p[2 * j + 1] = pack2(v[j].y, v[j].y);
                }
                const bool oy0 = (yin <= 4), oy1 = (yin >= 1);
#pragma unroll
                for (int oz = 0; oz < 2; oz++) {
                    if (oz ? !oz1 : !oz0) continue;
                    const int kz = zin - oz;
#pragma unroll
                    for (int oy = 0; oy < 2; oy++) {
                        if (oy ? !oy1 : !oy0) continue;
                        const int ky = yin - oy;
                        const ull* wr = &ws[((ic * 5 + kz) * 5 + ky) * 6];
                        const ulonglong2 wab = *(const ulonglong2*)wr;
                        const ulonglong2 wcd = *(const ulonglong2*)(wr + 2);
                        const ull W4 = wr[4];
#pragma unroll
                        for (int pxl = 0; pxl < 3; pxl++) {
#pragma unroll
                            for (int ox = 0; ox < 2; ox++) {
                                ull& A = acc[pxl][ox][oz][oy];
                                const int b = 2 * pxl + ox;
                                fma2(A, wab.x, p[b + 0]);
                                fma2(A, wab.y, p[b + 1]);
                                fma2(A, wcd.x, p[b + 2]);
                                fma2(A, wcd.y, p[b + 3]);
                                fma2(A, W4,    p[b + 4]);
                            }
                        }
                    }
                }
            }
        }
    }
#pragma unroll
    for (int pxl = 0; pxl < 3; pxl++) {
        float m0 = -CUDART_INF_F, m1 = -CUDART_INF_F;
#pragma unroll
        for (int ox = 0; ox < 2; ox++)
#pragma unroll
            for (int oz = 0; oz < 2; oz++)
#pragma unroll
                for (int oy = 0; oy < 2; oy++) {
                    const float2 v = unpack2(acc[pxl][ox][oz][oy]);
                    m0 = fmaxf(m0, v.x);
                    m1 = fmaxf(m1, v.y);
                }
        m0 += sb[0]; m1 += sb[1];
        const float v0 = (m0 >= 0.0f) ? m0 : sa * m0;
        const float v1 = (m1 >= 0.0f) ? m1 : sa * m1;
        const int px = 3 * tx + pxl;
        out[(((size_t)(n * 32 + cg * 2 + 0) * 23 + pz + 1) * 23 + py + 1) * 24 + px + 1] = v0;
        out[(((size_t)(n * 32 + cg * 2 + 1) * 23 + pz + 1) * 23 + py + 1) * 24 + px + 1] = v1;
    }
}

// ---------------- conv1: 32->32, k5, pad1, fused pool2 ----------------
// f32x2 over CHANNEL PAIR, padded gmem input -> unconditional LDG.64.
// grid (16 cg, 80 n), block (3 tx, 9 py, 9 pz)
__global__ void conv1_kernel(const float* __restrict__ xpad,
                             const float* __restrict__ w,
                             const float* __restrict__ bias,
                             const float* __restrict__ prelu,
                             float* __restrict__ out) {
    const int cg = blockIdx.x, n = blockIdx.y;
    const int tx = threadIdx.x, py = threadIdx.y, pz = threadIdx.z;
    __shared__ __align__(16) ull ws[32 * 5 * 5 * 6];  // 38.4KB channel pairs
    __shared__ float sb[2];
    __shared__ float sa;
    const int tid = (pz * 9 + py) * 3 + tx;
    for (int i = tid; i < 4000; i += 243) {
        const int ic = i / 125, rr = i % 125;
        const int kz = rr / 25, ky = (rr / 5) % 5, kx = rr % 5;
        const float w0 = w[(cg * 2 + 0) * 4000 + i];
        const float w1 = w[(cg * 2 + 1) * 4000 + i];
        ws[((ic * 5 + kz) * 5 + ky) * 6 + kx] = pack2(w0, w1);
    }
    if (tid < 2) sb[tid] = bias[cg * 2 + tid];
    if (tid == 0) sa = prelu[0];
    __syncthreads();

    ull acc[3][2][2][2] = {};

    for (int ic = 0; ic < 32; ic++) {
        const float* base = xpad + ((size_t)(n * 32 + ic)) * (23 * 23 * 24);
#pragma unroll 2
        for (int zin = 0; zin < 6; zin++) {
            const int zp = 2 * pz + zin;
            const bool oz0 = (zin <= 4), oz1 = (zin >= 1);
#pragma unroll
            for (int yin = 0; yin < 6; yin++) {
                const int yp = 2 * py + yin;
                const float2* rp = (const float2*)(base + ((size_t)zp * 23 + yp) * 24 + 6 * tx);
                float2 v[5];
#pragma unroll
                for (int j = 0; j < 5; j++) v[j] = __ldg(rp + j);
                ull p[10];
#pragma unroll
                for (int j = 0; j < 5; j++) {
                    p[2 * j + 0] = pack2(v[j].x, v[j].x);
                    p[2 * j + 1] = pack2(v[j].y, v[j].y);
                }
                const bool oy0 = (yin <= 4), oy1 = (yin >= 1);
#pragma unroll
                for (int oz = 0; oz < 2; oz++) {
                    if (oz ? !oz1 : !oz0) continue;
                    const int kz = zin - oz;
#pragma unroll
                    for (int oy = 0; oy < 2; oy++) {
                        if (oy ? !oy1 : !oy0) continue;
                        const int ky = yin - oy;
                        const ull* wr = &ws[((ic * 5 + kz) * 5 + ky) * 6];
                        const ulonglong2 wab = *(const ulonglong2*)wr;
                        const ulonglong2 wcd = *(const ulonglong2*)(wr + 2);
                        const ull W4 = wr[4];
#pragma unroll
                        for (int pxl = 0; pxl < 3; pxl++) {
#pragma unroll
                            for (int ox = 0; ox < 2; ox++) {
                                ull& A = acc[pxl][ox][oz][oy];
                                const int b = 2 * pxl + ox;
                                fma2(A, wab.x, p[b + 0]);
                                fma2(A, wab.y, p[b + 1]);
                                fma2(A, wcd.x, p[b + 2]);
                                fma2(A, wcd.y, p[b + 3]);
                                fma2(A, W4,    p[b + 4]);
                            }
                        }
                    }
                }
            }
        }
    }
#pragma unroll
    for (int pxl = 0; pxl < 3; pxl++) {
        float m0 = -CUDART_INF_F, m1 = -CUDART_INF_F;
#pragma unroll
        for (int ox = 0; ox < 2; ox++)
#pragma unroll
            for (int oz = 0; oz < 2; oz++)
#pragma unroll
                for (int oy = 0; oy < 2; oy++) {
                    const float2 v = unpack2(acc[pxl][ox][oz][oy]);
                    m0 = fmaxf(m0, v.x);
                    m1 = fmaxf(m1, v.y);
                }
        m0 += sb[0]; m1 += sb[1];
        const float v0 = (m0 >= 0.0f) ? m0 : sa * m0;
        const float v1 = (m1 >= 0.0f) ? m1 : sa * m1;
        const int px = 3 * tx + pxl;
        out[(((size_t)(n * 32 + cg * 2 + 0) * 11 + pz + 1) * 11 + py + 1) * 12 + px + 1] = v0;
        out[(((size_t)(n * 32 + cg * 2 + 1) * 11 + pz + 1) * 11 + py + 1) * 12 + px + 1] = v1;
    }
}

// ---------------- conv2: 32->64, k4, pad1, fused pool2, f32x2 over ox ----------------
// Input slab staged in smem via contiguous float4 copy (fixes scattered-LDG L1 bound).
// grid (16 cgroup, 80 n), block (4 py, 4 pz, 4 c4)
__global__ void conv2_kernel(const float* __restrict__ xpad,
                             const float* __restrict__ w,
                             const float* __restrict__ bias,
                             const float* __restrict__ prelu,
                             float* __restrict__ out) {
    const int bx = blockIdx.x, n = blockIdx.y;
    const int py = threadIdx.x, pz = threadIdx.y, c4 = threadIdx.z;
    __shared__ __align__(16) float ws[4 * 2048];   // [c4][ic][kz][ky][kx], 32KB
    __shared__ __align__(16) float slab[1452];     // padded [11][11][12] ic-slab, 5.8KB
    __shared__ float sb[4];
    __shared__ float sa;
    const int tid = (c4 * 4 + pz) * 4 + py;
    for (int i = tid; i < 8192; i += 64) ws[i] = w[(size_t)bx * 8192 + i];
    if (tid < 4) sb[tid] = bias[bx * 4 + tid];
    if (tid == 0) sa = prelu[0];

    ull acc[4][2][2] = {};  // [px][oz][oy], f32x2 over ox

    for (int ic = 0; ic < 32; ic++) {
        __syncthreads();
        {   // contiguous staged copy: 1452 floats = 363 float4
            const float4* src = (const float4*)(xpad + ((size_t)(n * 32 + ic)) * 1452);
            float4* dst = (float4*)slab;
            for (int i = tid; i < 363; i += 64) dst[i] = __ldg(src + i);
        }
        __syncthreads();
#pragma unroll
        for (int zin = 0; zin < 5; zin++) {
            const int zp = 2 * pz + zin;
            const bool oz0 = (zin <= 3), oz1 = (zin >= 1);
#pragma unroll
            for (int yin = 0; yin < 5; yin++) {
                const int yp = 2 * py + yin;
                const float* row = slab + (zp * 11 + yp) * 12;
                float in[11];
#pragma unroll
                for (int j = 0; j < 11; j++) in[j] = row[j];
                ull p[10];
#pragma unroll
                for (int i = 0; i < 10; i++) p[i] = pack2(in[i], in[i + 1]);
                const bool oy0 = (yin <= 3), oy1 = (yin >= 1);
#pragma unroll
                for (int oz = 0; oz < 2; oz++) {
                    if (oz ? !oz1 : !oz0) continue;
                    const int kz = zin - oz;
#pragma unroll
                    for (int oy = 0; oy < 2; oy++) {
                        if (oy ? !oy1 : !oy0) continue;
                        const int ky = yin - oy;
                        const float* wr = &ws[((c4 * 32 + ic) * 16 + kz * 4 + ky) * 4];
                        const float4 w4 = *(const float4*)wr;
                        const ull W0 = pack2(w4.x, w4.x), W1 = pack2(w4.y, w4.y),
                                  W2 = pack2(w4.z, w4.z), W3 = pack2(w4.w, w4.w);
#pragma unroll
                        for (int px = 0; px < 4; px++) {
                            ull& A = acc[px][oz][oy];
                            fma2(A, W0, p[2 * px + 0]);
                            fma2(A, W1, p[2 * px + 1]);
                            fma2(A, W2, p[2 * px + 2]);
                            fma2(A, W3, p[2 * px + 3]);
                        }
                    }
                }
            }
        }
    }
    const float b = sb[c4];
#pragma unroll
    for (int px = 0; px < 4; px++) {
        float m = -CUDART_INF_F;
#pragma unroll
        for (int oz = 0; oz < 2; oz++)
#pragma unroll
            for (int oy = 0; oy < 2; oy++) {
                const float2 v = unpack2(acc[px][oz][oy]);
                m = fmaxf(m, fmaxf(v.x, v.y));
            }
        m += b;
        const float v = (m >= 0.0f) ? m : sa * m;
        out[(((size_t)(n * 64 + bx * 4 + c4) * 4 + pz) * 4 + py) * 4 + px] = v;
    }
}

// ---------------- conv3: 64->64, k3, pad0, + reshape to feat ----------------
__global__ void conv3_kernel(const float* __restrict__ x,
                             const float* __restrict__ w,
                             const float* __restrict__ bias,
                             const float* __restrict__ prelu,
                             float* __restrict__ feat) {
    const int n = blockIdx.x;
    const int tid = threadIdx.x;
    __shared__ float sin[64 * 64];  // [ic][z*16+y*4+x]
    for (int i = tid; i < 4096; i += 512) sin[i] = x[(size_t)n * 4096 + i];
    __syncthreads();

    const int c = tid >> 3, s = tid & 7;
    const int oz = s >> 2, oy = (s >> 1) & 1, ox = s & 1;
    float acc = bias[c];
    const float* wc = w + (size_t)c * 64 * 27;
    for (int ic = 0; ic < 64; ic++) {
        const float* si = sin + ic * 64;
        const float* wi = wc + ic * 27;
#pragma unroll
        for (int kz = 0; kz < 3; kz++)
#pragma unroll
            for (int ky = 0; ky < 3; ky++)
#pragma unroll
                for (int kx = 0; kx < 3; kx++)
                    acc = fmaf(__ldg(wi + (kz * 3 + ky) * 3 + kx),
                               si[(oz + kz) * 16 + (oy + ky) * 4 + (ox + kx)], acc);
    }
    const float a = prelu[0];
    const float v = (acc >= 0.0f) ? acc : a * acc;
    feat[(size_t)n * 512 + c * 8 + s] = v;
}

// ---------------- mean over agents ----------------
__global__ void mean_kernel(const float* __restrict__ feat, float* __restrict__ mean, int D) {
    const int b = blockIdx.x, i = threadIdx.x;
    float s = 0.0f;
    for (int a = 0; a < 5; a++) s += feat[((size_t)(b * 5 + a)) * D + i];
    mean[(size_t)b * D + i] = s * (1.0f / 5.0f);
}

// ---------------- comm fc: warp-per-output, coalesced float4 ----------------
// grid (80, ceil(O/8)), block 256 (8 warps)
__global__ void commfc_kernel(const float* __restrict__ feat,
                              const float* __restrict__ mean,
                              const float* __restrict__ w,
                              const float* __restrict__ bias,
                              const float* __restrict__ prelu,
                              float* __restrict__ out, int D, int O) {
    const int bx = blockIdx.x;
    const int b = bx / 5, a = bx % 5;
    const int warp = threadIdx.x >> 5, lane = threadIdx.x & 31;
    const int o = blockIdx.y * 8 + warp;
    if (o >= O) return;
    const int D4 = D >> 2;
    const float4* fp = (const float4*)(feat + (size_t)bx * D);
    const float4* mp = (const float4*)(mean + (size_t)b * D);
    const float4* wp = (const float4*)(w + ((size_t)a * O + o) * (2 * D));
    float acc = 0.0f;
    for (int i = lane; i < D4; i += 32) {
        const float4 f = fp[i];
        const float4 wv = __ldg(wp + i);
        acc += f.x * wv.x + f.y * wv.y + f.z * wv.z + f.w * wv.w;
    }
    for (int i = lane; i < D4; i += 32) {
        const float4 m = mp[i];
        const float4 wv = __ldg(wp + D4 + i);
        acc += m.x * wv.x + m.y * wv.y + m.z * wv.z + m.w * wv.w;
    }
#pragma unroll
    for (int s = 16; s > 0; s >>= 1) acc += __shfl_xor_sync(0xffffffffu, acc, s);
    if (lane == 0) {
        acc += bias[a * O + o];
        if (prelu) {
            const float al = prelu[0];
            acc = (acc >= 0.0f) ? acc : al * acc;
        }
        out[(size_t)bx * O + o] = acc;
    }
}

extern "C" void kernel_launch(void* const* d_in, const int* in_sizes, int n_in,
                              void* d_out, int out_size) {
    const float* x        = (const float*)d_in[0];
    const float* conv0_w  = (const float*)d_in[1];
    const float* conv0_b  = (const float*)d_in[2];
    const float* prelu0   = (const float*)d_in[3];
    const float* conv1_w  = (const float*)d_in[4];
    const float* conv1_b  = (const float*)d_in[5];
    const float* prelu1   = (const float*)d_in[6];
    const float* conv2_w  = (const float*)d_in[7];
    const float* conv2_b  = (const float*)d_in[8];
    const float* prelu2   = (const float*)d_in[9];
    const float* conv3_w  = (const float*)d_in[10];
    const float* conv3_b  = (const float*)d_in[11];
    const float* prelu3   = (const float*)d_in[12];
    const float* fc1_w    = (const float*)d_in[13];
    const float* fc1_b    = (const float*)d_in[14];
    const float* prelu4   = (const float*)d_in[15];
    const float* fc2_w    = (const float*)d_in[16];
    const float* fc2_b    = (const float*)d_in[17];
    const float* prelu5   = (const float*)d_in[18];
    const float* fc3_w    = (const float*)d_in[19];
    const float* fc3_b    = (const float*)d_in[20];
    float* out = (float*)d_out;

    float *xpad, *buf0, *buf1, *buf2, *feat, *mean1, *fc1, *mean2, *fc2, *mean3;
    cudaGetSymbolAddress((void**)&xpad,  g_xpad);
    cudaGetSymbolAddress((void**)&buf0,  g_buf0);
    cudaGetSymbolAddress((void**)&buf1,  g_buf1);
    cudaGetSymbolAddress((void**)&buf2,  g_buf2);
    cudaGetSymbolAddress((void**)&feat,  g_feat);
    cudaGetSymbolAddress((void**)&mean1, g_mean1);
    cudaGetSymbolAddress((void**)&fc1,   g_fc1);
    cudaGetSymbolAddress((void**)&mean2, g_mean2);
    cudaGetSymbolAddress((void**)&fc2,   g_fc2);
    cudaGetSymbolAddress((void**)&mean3, g_mean3);

    const size_t xtotal = 80u * 4u * 45u * 45u * 45u;
    pad_x_kernel<<<(unsigned)((xtotal + 255) / 256), 256>>>(x, xpad);

    conv0_kernel<<<dim3(21, 16, NN), dim3(7, 21)>>>(xpad, conv0_w, conv0_b, prelu0, buf0);
    conv1_kernel<<<dim3(16, NN), dim3(3, 9, 9)>>>(buf0, conv1_w, conv1_b, prelu1, buf1);
    conv2_kernel<<<dim3(16, NN), dim3(4, 4, 4)>>>(buf1, conv2_w, conv2_b, prelu2, buf2);
    conv3_kernel<<<NN, 512>>>(buf2, conv3_w, conv3_b, prelu3, feat);

    mean_kernel<<<16, 512>>>(feat, mean1, 512);
    commfc_kernel<<<dim3(NN, 32), 256>>>(feat, mean1, fc1_w, fc1_b, prelu4, fc1, 512, 256);
    mean_kernel<<<16, 256>>>(fc1, mean2, 256);
    commfc_kernel<<<dim3(NN, 16), 256>>>(fc1, mean2, fc2_w, fc2_b, prelu5, fc2, 256, 128);
    mean_kernel<<<16, 128>>>(fc2, mean3, 128);
    commfc_kernel<<<dim3(NN, 1), 256>>>(fc2, mean3, fc3_w, fc3_b, nullptr, out, 128, 6);
}

// round 10
// speedup vs baseline: 1.5837x; 1.0100x over previous
#include <cuda_runtime.h>
#include <cuda_bf16.h>
#include <math_constants.h>

// ---------------- shapes ----------------
// B=16, A=5 -> N = 80 folded batch
// conv0: 4->32 k5 p1 : 45 -> 43 -> pool 21
// conv1: 32->32 k5 p1: 21 -> 19 -> pool 9
// conv2: 32->64 k4 p1: 9  -> 8  -> pool 4
// conv3: 64->64 k3 p0: 4  -> 2          -> feat [80,512]
// fc1: 1024->256, fc2: 512->128, fc3: 256->6 (per-agent, mean-comm concat)
//
// Zero-padded GMEM intermediates (halos never written; __device__ globals are
// zero-initialized) -> conv input loads are unconditional aligned LDG.64.

#define NN 80

typedef unsigned long long ull;

__device__ __forceinline__ ull pack2(float lo, float hi) {
    ull r; asm("mov.b64 %0, {%1, %2};" : "=l"(r) : "f"(lo), "f"(hi)); return r;
}
__device__ __forceinline__ void fma2(ull& d, ull a, ull b) {
    asm("fma.rn.f32x2 %0, %1, %2, %0;" : "+l"(d) : "l"(a), "l"(b));
}
__device__ __forceinline__ float2 unpack2(ull v) {
    float2 f; asm("mov.b64 {%0, %1}, %2;" : "=f"(f.x), "=f"(f.y) : "l"(v)); return f;
}

// padded tensors (halo = zero, never written)
__device__ float g_xpad[80u * 4u * 47u * 47u * 48u];    // 135.7 MB, [n][ic][47][47][48]
__device__ float g_buf0[80u * 32u * 23u * 23u * 24u];   // 130 MB,   [n][c][23][23][24]
__device__ float g_buf1[80u * 32u * 11u * 11u * 12u];   // 14.9 MB,  [n][c][11][11][12]
__device__ float g_buf2[80u * 64u * 4u * 4u * 4u];
__device__ float g_feat[80u * 512u];
__device__ float g_mean1[16u * 512u];
__device__ float g_fc1[80u * 256u];
__device__ float g_mean2[16u * 256u];
__device__ float g_fc2[80u * 128u];
__device__ float g_mean3[16u * 128u];

// ---------------- pad x into g_xpad interior ----------------
__global__ void pad_x_kernel(const float* __restrict__ x, float* __restrict__ xp) {
    const size_t i = (size_t)blockIdx.x * blockDim.x + threadIdx.x;
    const size_t total = 80u * 4u * 45u * 45u * 45u;
    if (i >= total) return;
    const int xc = (int)(i % 45);
    size_t t = i / 45;
    const int y = (int)(t % 45); t /= 45;
    const int z = (int)(t % 45);
    const int nc = (int)(t / 45);
    xp[(((size_t)nc * 47 + (z + 1)) * 47 + (y + 1)) * 48 + (xc + 1)] = x[i];
}

// ---------------- conv0: 4->32, k5, pad1, fused pool2 ----------------
// f32x2 over CHANNEL PAIR, padded gmem input -> unconditional LDG.64.
// grid (21 pz, 16 cg, 80 n), block (7 tx, 21 py)
__global__ void conv0_kernel(const float* __restrict__ xp,
                             const float* __restrict__ w,
                             const float* __restrict__ bias,
                             const float* __restrict__ prelu,
                             float* __restrict__ out) {
    const int pz = blockIdx.x, cg = blockIdx.y, n = blockIdx.z;
    const int tx = threadIdx.x, py = threadIdx.y;
    __shared__ __align__(16) ull ws[4 * 5 * 5 * 6];  // channel pairs, kx padded->6
    __shared__ float sb[2];
    __shared__ float sa;
    const int tid = py * 7 + tx;
    for (int i = tid; i < 500; i += 147) {
        const int ic = i / 125, rr = i % 125;
        const int kz = rr / 25, ky = (rr / 5) % 5, kx = rr % 5;
        const float w0 = w[(cg * 2 + 0) * 500 + i] * (1.0f / 255.0f);
        const float w1 = w[(cg * 2 + 1) * 500 + i] * (1.0f / 255.0f);
        ws[((ic * 5 + kz) * 5 + ky) * 6 + kx] = pack2(w0, w1);
    }
    if (tid < 2) sb[tid] = bias[cg * 2 + tid];
    if (tid == 0) sa = prelu[0];
    __syncthreads();

    ull acc[3][2][2][2] = {};  // [pxl][ox][oz][oy], f32x2 over channel pair

    for (int ic = 0; ic < 4; ic++) {
        const float* base = xp + ((size_t)(n * 4 + ic)) * (47 * 47 * 48);
        for (int zin = 0; zin < 6; zin++) {
            const int zp = 2 * pz + zin;  // padded z, always in range
            const bool oz0 = (zin <= 4), oz1 = (zin >= 1);
#pragma unroll
            for (int yin = 0; yin < 6; yin++) {
                const int yp = 2 * py + yin;
                const float2* rp = (const float2*)(base + ((size_t)zp * 47 + yp) * 48 + 6 * tx);
                float2 v[5];
#pragma unroll
                for (int j = 0; j < 5; j++) v[j] = __ldg(rp + j);
                ull p[10];
#pragma unroll
                for (int j = 0; j < 5; j++) {
                    p[2 * j + 0] = pack2(v[j].x, v[j].x);
                    p[2 * j + 1] = pack2(v[j].y, v[j].y);
                }
                const bool oy0 = (yin <= 4), oy1 = (yin >= 1);
#pragma unroll
                for (int oz = 0; oz < 2; oz++) {
                    if (oz ? !oz1 : !oz0) continue;
                    const int kz = zin - oz;
#pragma unroll
                    for (int oy = 0; oy < 2; oy++) {
                        if (oy ? !oy1 : !oy0) continue;
                        const int ky = yin - oy;
                        const ull* wr = &ws[((ic * 5 + kz) * 5 + ky) * 6];
                        const ulonglong2 wab = *(const ulonglong2*)wr;
                        const ulonglong2 wcd = *(const ulonglong2*)(wr + 2);
                        const ull W4 = wr[4];
#pragma unroll
                        for (int pxl = 0; pxl < 3; pxl++) {
#pragma unroll
                            for (int ox = 0; ox < 2; ox++) {
                                ull& A = acc[pxl][ox][oz][oy];
                                const int b = 2 * pxl + ox;
                                fma2(A, wab.x, p[b + 0]);
                                fma2(A, wab.y, p[b + 1]);
                                fma2(A, wcd.x, p[b + 2]);
                                fma2(A, wcd.y, p[b + 3]);
                                fma2(A, W4,    p[b + 4]);
                            }
                        }
                    }
                }
            }
        }
    }
#pragma unroll
    for (int pxl = 0; pxl < 3; pxl++) {
        float m0 = -CUDART_INF_F, m1 = -CUDART_INF_F;
#pragma unroll
        for (int ox = 0; ox < 2; ox++)
#pragma unroll
            for (int oz = 0; oz < 2; oz++)
#pragma unroll
                for (int oy = 0; oy < 2; oy++) {
                    const float2 v = unpack2(acc[pxl][ox][oz][oy]);
                    m0 = fmaxf(m0, v.x);
                    m1 = fmaxf(m1, v.y);
                }
        m0 += sb[0]; m1 += sb[1];
        const float v0 = (m0 >= 0.0f) ? m0 : sa * m0;
        const float v1 = (m1 >= 0.0f) ? m1 : sa * m1;
        const int px = 3 * tx + pxl;
        out[(((size_t)(n * 32 + cg * 2 + 0) * 23 + pz + 1) * 23 + py + 1) * 24 + px + 1] = v0;
        out[(((size_t)(n * 32 + cg * 2 + 1) * 23 + pz + 1) * 23 + py + 1) * 24 + px + 1] = v1;
    }
}

// ---------------- conv1: 32->32, k5, pad1, fused pool2 ----------------
// f32x2 over CHANNEL PAIR, padded gmem input -> unconditional LDG.64.
// grid (16 cg, 80 n), block (3 tx, 9 py, 9 pz)
__global__ void conv1_kernel(const float* __restrict__ xpad,
                             const float* __restrict__ w,
                             const float* __restrict__ bias,
                             const float* __restrict__ prelu,
                             float* __restrict__ out) {
    const int cg = blockIdx.x, n = blockIdx.y;
    const int tx = threadIdx.x, py = threadIdx.y, pz = threadIdx.z;
    __shared__ __align__(16) ull ws[32 * 5 * 5 * 6];  // 38.4KB channel pairs
    __shared__ float sb[2];
    __shared__ float sa;
    const int tid = (pz * 9 + py) * 3 + tx;
    for (int i = tid; i < 4000; i += 243) {
        const int ic = i / 125, rr = i % 125;
        const int kz = rr / 25, ky = (rr / 5) % 5, kx = rr % 5;
        const float w0 = w[(cg * 2 + 0) * 4000 + i];
        const float w1 = w[(cg * 2 + 1) * 4000 + i];
        ws[((ic * 5 + kz) * 5 + ky) * 6 + kx] = pack2(w0, w1);
    }
    if (tid < 2) sb[tid] = bias[cg * 2 + tid];
    if (tid == 0) sa = prelu[0];
    __syncthreads();

    ull acc[3][2][2][2] = {};

    for (int ic = 0; ic < 32; ic++) {
        const float* base = xpad + ((size_t)(n * 32 + ic)) * (23 * 23 * 24);
#pragma unroll 2
        for (int zin = 0; zin < 6; zin++) {
            const int zp = 2 * pz + zin;
            const bool oz0 = (zin <= 4), oz1 = (zin >= 1);
#pragma unroll
            for (int yin = 0; yin < 6; yin++) {
                const int yp = 2 * py + yin;
                const float2* rp = (const float2*)(base + ((size_t)zp * 23 + yp) * 24 + 6 * tx);
                float2 v[5];
#pragma unroll
                for (int j = 0; j < 5; j++) v[j] = __ldg(rp + j);
                ull p[10];
#pragma unroll
                for (int j = 0; j < 5; j++) {
                    p[2 * j + 0] = pack2(v[j].x, v[j].x);
                    p[2 * j + 1] = pack2(v[j].y, v[j].y);
                }
                const bool oy0 = (yin <= 4), oy1 = (yin >= 1);
#pragma unroll
                for (int oz = 0; oz < 2; oz++) {
                    if (oz ? !oz1 : !oz0) continue;
                    const int kz = zin - oz;
#pragma unroll
                    for (int oy = 0; oy < 2; oy++) {
                        if (oy ? !oy1 : !oy0) continue;
                        const int ky = yin - oy;
                        const ull* wr = &ws[((ic * 5 + kz) * 5 + ky) * 6];
                        const ulonglong2 wab = *(const ulonglong2*)wr;
                        const ulonglong2 wcd = *(const ulonglong2*)(wr + 2);
                        const ull W4 = wr[4];
#pragma unroll
                        for (int pxl = 0; pxl < 3; pxl++) {
#pragma unroll
                            for (int ox = 0; ox < 2; ox++) {
                                ull& A = acc[pxl][ox][oz][oy];
                                const int b = 2 * pxl + ox;
                                fma2(A, wab.x, p[b + 0]);
                                fma2(A, wab.y, p[b + 1]);
                                fma2(A, wcd.x, p[b + 2]);
                                fma2(A, wcd.y, p[b + 3]);
                                fma2(A, W4,    p[b + 4]);
                            }
                        }
                    }
                }
            }
        }
    }
#pragma unroll
    for (int pxl = 0; pxl < 3; pxl++) {
        float m0 = -CUDART_INF_F, m1 = -CUDART_INF_F;
#pragma unroll
        for (int ox = 0; ox < 2; ox++)
#pragma unroll
            for (int oz = 0; oz < 2; oz++)
#pragma unroll
                for (int oy = 0; oy < 2; oy++) {
                    const float2 v = unpack2(acc[pxl][ox][oz][oy]);
                    m0 = fmaxf(m0, v.x);
                    m1 = fmaxf(m1, v.y);
                }
        m0 += sb[0]; m1 += sb[1];
        const float v0 = (m0 >= 0.0f) ? m0 : sa * m0;
        const float v1 = (m1 >= 0.0f) ? m1 : sa * m1;
        const int px = 3 * tx + pxl;
        out[(((size_t)(n * 32 + cg * 2 + 0) * 11 + pz + 1) * 11 + py + 1) * 12 + px + 1] = v0;
        out[(((size_t)(n * 32 + cg * 2 + 1) * 11 + pz + 1) * 11 + py + 1) * 12 + px + 1] = v1;
    }
}

// ---------------- conv2: 32->64, k4, pad1, fused pool2, f32x2 over ox ----------------
// Input slab staged in smem via contiguous float4 copy (fixes scattered-LDG L1 bound).
// grid (16 cgroup, 80 n), block (4 py, 4 pz, 4 c4)
__global__ void conv2_kernel(const float* __restrict__ xpad,
                             const float* __restrict__ w,
                             const float* __restrict__ bias,
                             const float* __restrict__ prelu,
                             float* __restrict__ out) {
    const int bx = blockIdx.x, n = blockIdx.y;
    const int py = threadIdx.x, pz = threadIdx.y, c4 = threadIdx.z;
    __shared__ __align__(16) float ws[4 * 2048];   // [c4][ic][kz][ky][kx], 32KB
    __shared__ __align__(16) float slab[1452];     // padded [11][11][12] ic-slab, 5.8KB
    __shared__ float sb[4];
    __shared__ float sa;
    const int tid = (c4 * 4 + pz) * 4 + py;
    for (int i = tid; i < 8192; i += 64) ws[i] = w[(size_t)bx * 8192 + i];
    if (tid < 4) sb[tid] = bias[bx * 4 + tid];
    if (tid == 0) sa = prelu[0];

    ull acc[4][2][2] = {};  // [px][oz][oy], f32x2 over ox

    for (int ic = 0; ic < 32; ic++) {
        __syncthreads();
        {   // contiguous staged copy: 1452 floats = 363 float4
            const float4* src = (const float4*)(xpad + ((size_t)(n * 32 + ic)) * 1452);
            float4* dst = (float4*)slab;
            for (int i = tid; i < 363; i += 64) dst[i] = __ldg(src + i);
        }
        __syncthreads();
#pragma unroll
        for (int zin = 0; zin < 5; zin++) {
            const int zp = 2 * pz + zin;
            const bool oz0 = (zin <= 3), oz1 = (zin >= 1);
#pragma unroll
            for (int yin = 0; yin < 5; yin++) {
                const int yp = 2 * py + yin;
                const float* row = slab + (zp * 11 + yp) * 12;
                float in[11];
#pragma unroll
                for (int j = 0; j < 11; j++) in[j] = row[j];
                ull p[10];
#pragma unroll
                for (int i = 0; i < 10; i++) p[i] = pack2(in[i], in[i + 1]);
                const bool oy0 = (yin <= 3), oy1 = (yin >= 1);
#pragma unroll
                for (int oz = 0; oz < 2; oz++) {
                    if (oz ? !oz1 : !oz0) continue;
                    const int kz = zin - oz;
#pragma unroll
                    for (int oy = 0; oy < 2; oy++) {
                        if (oy ? !oy1 : !oy0) continue;
                        const int ky = yin - oy;
                        const float* wr = &ws[((c4 * 32 + ic) * 16 + kz * 4 + ky) * 4];
                        const float4 w4 = *(const float4*)wr;
                        const ull W0 = pack2(w4.x, w4.x), W1 = pack2(w4.y, w4.y),
                                  W2 = pack2(w4.z, w4.z), W3 = pack2(w4.w, w4.w);
#pragma unroll
                        for (int px = 0; px < 4; px++) {
                            ull& A = acc[px][oz][oy];
                            fma2(A, W0, p[2 * px + 0]);
                            fma2(A, W1, p[2 * px + 1]);
                            fma2(A, W2, p[2 * px + 2]);
                            fma2(A, W3, p[2 * px + 3]);
                        }
                    }
                }
            }
        }
    }
    const float b = sb[c4];
#pragma unroll
    for (int px = 0; px < 4; px++) {
        float m = -CUDART_INF_F;
#pragma unroll
        for (int oz = 0; oz < 2; oz++)
#pragma unroll
            for (int oy = 0; oy < 2; oy++) {
                const float2 v = unpack2(acc[px][oz][oy]);
                m = fmaxf(m, fmaxf(v.x, v.y));
            }
        m += b;
        const float v = (m >= 0.0f) ? m : sa * m;
        out[(((size_t)(n * 64 + bx * 4 + c4) * 4 + pz) * 4 + py) * 4 + px] = v;
    }
}

// ---------------- conv3: 64->64, k3, pad0, + reshape to feat ----------------
__global__ void conv3_kernel(const float* __restrict__ x,
                             const float* __restrict__ w,
                             const float* __restrict__ bias,
                             const float* __restrict__ prelu,
                             float* __restrict__ feat) {
    const int n = blockIdx.x;
    const int tid = threadIdx.x;
    __shared__ float sin[64 * 64];  // [ic][z*16+y*4+x]
    for (int i = tid; i < 4096; i += 512) sin[i] = x[(size_t)n * 4096 + i];
    __syncthreads();

    const int c = tid >> 3, s = tid & 7;
    const int oz = s >> 2, oy = (s >> 1) & 1, ox = s & 1;
    float acc = bias[c];
    const float* wc = w + (size_t)c * 64 * 27;
    for (int ic = 0; ic < 64; ic++) {
        const float* si = sin + ic * 64;
        const float* wi = wc + ic * 27;
#pragma unroll
        for (int kz = 0; kz < 3; kz++)
#pragma unroll
            for (int ky = 0; ky < 3; ky++)
#pragma unroll
                for (int kx = 0; kx < 3; kx++)
                    acc = fmaf(__ldg(wi + (kz * 3 + ky) * 3 + kx),
                               si[(oz + kz) * 16 + (oy + ky) * 4 + (ox + kx)], acc);
    }
    const float a = prelu[0];
    const float v = (acc >= 0.0f) ? acc : a * acc;
    feat[(size_t)n * 512 + c * 8 + s] = v;
}

// ---------------- mean over agents ----------------
__global__ void mean_kernel(const float* __restrict__ feat, float* __restrict__ mean, int D) {
    const int b = blockIdx.x, i = threadIdx.x;
    float s = 0.0f;
    for (int a = 0; a < 5; a++) s += feat[((size_t)(b * 5 + a)) * D + i];
    mean[(size_t)b * D + i] = s * (1.0f / 5.0f);
}

// ---------------- comm fc: warp-per-output, coalesced float4 ----------------
// grid (80, ceil(O/8)), block 256 (8 warps)
__global__ void commfc_kernel(const float* __restrict__ feat,
                              const float* __restrict__ mean,
                              const float* __restrict__ w,
                              const float* __restrict__ bias,
                              const float* __restrict__ prelu,
                              float* __restrict__ out, int D, int O) {
    const int bx = blockIdx.x;
    const int b = bx / 5, a = bx % 5;
    const int warp = threadIdx.x >> 5, lane = threadIdx.x & 31;
    const int o = blockIdx.y * 8 + warp;
    if (o >= O) return;
    const int D4 = D >> 2;
    const float4* fp = (const float4*)(feat + (size_t)bx * D);
    const float4* mp = (const float4*)(mean + (size_t)b * D);
    const float4* wp = (const float4*)(w + ((size_t)a * O + o) * (2 * D));
    float acc = 0.0f;
    for (int i = lane; i < D4; i += 32) {
        const float4 f = fp[i];
        const float4 wv = __ldg(wp + i);
        acc += f.x * wv.x + f.y * wv.y + f.z * wv.z + f.w * wv.w;
    }
    for (int i = lane; i < D4; i += 32) {
        const float4 m = mp[i];
        const float4 wv = __ldg(wp + D4 + i);
        acc += m.x * wv.x + m.y * wv.y + m.z * wv.z + m.w * wv.w;
    }
#pragma unroll
    for (int s = 16; s > 0; s >>= 1) acc += __shfl_xor_sync(0xffffffffu, acc, s);
    if (lane == 0) {
        acc += bias[a * O + o];
        if (prelu) {
            const float al = prelu[0];
            acc = (acc >= 0.0f) ? acc : al * acc;
        }
        out[(size_t)bx * O + o] = acc;
    }
}

extern "C" void kernel_launch(void* const* d_in, const int* in_sizes, int n_in,
                              void* d_out, int out_size) {
    const float* x        = (const float*)d_in[0];
    const float* conv0_w  = (const float*)d_in[1];
    const float* conv0_b  = (const float*)d_in[2];
    const float* prelu0   = (const float*)d_in[3];
    const float* conv1_w  = (const float*)d_in[4];
    const float* conv1_b  = (const float*)d_in[5];
    const float* prelu1   = (const float*)d_in[6];
    const float* conv2_w  = (const float*)d_in[7];
    const float* conv2_b  = (const float*)d_in[8];
    const float* prelu2   = (const float*)d_in[9];
    const float* conv3_w  = (const float*)d_in[10];
    const float* conv3_b  = (const float*)d_in[11];
    const float* prelu3   = (const float*)d_in[12];
    const float* fc1_w    = (const float*)d_in[13];
    const float* fc1_b    = (const float*)d_in[14];
    const float* prelu4   = (const float*)d_in[15];
    const float* fc2_w    = (const float*)d_in[16];
    const float* fc2_b    = (const float*)d_in[17];
    const float* prelu5   = (const float*)d_in[18];
    const float* fc3_w    = (const float*)d_in[19];
    const float* fc3_b    = (const float*)d_in[20];
    float* out = (float*)d_out;

    float *xpad, *buf0, *buf1, *buf2, *feat, *mean1, *fc1, *mean2, *fc2, *mean3;
    cudaGetSymbolAddress((void**)&xpad,  g_xpad);
    cudaGetSymbolAddress((void**)&buf0,  g_buf0);
    cudaGetSymbolAddress((void**)&buf1,  g_buf1);
    cudaGetSymbolAddress((void**)&buf2,  g_buf2);
    cudaGetSymbolAddress((void**)&feat,  g_feat);
    cudaGetSymbolAddress((void**)&mean1, g_mean1);
    cudaGetSymbolAddress((void**)&fc1,   g_fc1);
    cudaGetSymbolAddress((void**)&mean2, g_mean2);
    cudaGetSymbolAddress((void**)&fc2,   g_fc2);
    cudaGetSymbolAddress((void**)&mean3, g_mean3);

    const size_t xtotal = 80u * 4u * 45u * 45u * 45u;
    pad_x_kernel<<<(unsigned)((xtotal + 255) / 256), 256>>>(x, xpad);

    conv0_kernel<<<dim3(21, 16, NN), dim3(7, 21)>>>(xpad, conv0_w, conv0_b, prelu0, buf0);
    conv1_kernel<<<dim3(16, NN), dim3(3, 9, 9)>>>(buf0, conv1_w, conv1_b, prelu1, buf1);
    conv2_kernel<<<dim3(16, NN), dim3(4, 4, 4)>>>(buf1, conv2_w, conv2_b, prelu2, buf2);
    conv3_kernel<<<NN, 512>>>(buf2, conv3_w, conv3_b, prelu3, feat);

    mean_kernel<<<16, 512>>>(feat, mean1, 512);
    commfc_kernel<<<dim3(NN, 32), 256>>>(feat, mean1, fc1_w, fc1_b, prelu4, fc1, 512, 256);
    mean_kernel<<<16, 256>>>(fc1, mean2, 256);
    commfc_kernel<<<dim3(NN, 16), 256>>>(fc1, mean2, fc2_w, fc2_b, prelu5, fc2, 256, 128);
    mean_kernel<<<16, 128>>>(fc2, mean3, 128);
    commfc_kernel<<<dim3(NN, 1), 256>>>(fc2, mean3, fc3_w, fc3_b, nullptr, out, 128, 6);
}

// round 17
// speedup vs baseline: 1.8128x; 1.1446x over previous
#include <cuda_runtime.h>
#include <cuda_bf16.h>
#include <math_constants.h>
#include <cstdint>

#define NN 80
typedef unsigned long long ull;

__device__ __forceinline__ ull pack2(float lo, float hi) {
    ull r; asm("mov.b64 %0, {%1, %2};" : "=l"(r) : "f"(lo), "f"(hi)); return r;
}
__device__ __forceinline__ void fma2(ull& d, ull a, ull b) {
    asm("fma.rn.f32x2 %0, %1, %2, %0;" : "+l"(d) : "l"(a), "l"(b));
}
__device__ __forceinline__ float2 unpack2(ull v) {
    float2 f; asm("mov.b64 {%0, %1}, %2;" : "=f"(f.x), "=f"(f.y) : "l"(v)); return f;
}
__device__ __forceinline__ void mma_bf16(float* d, const uint32_t* a, const uint32_t* b) {
    asm volatile(
        "mma.sync.aligned.m16n8k16.row.col.f32.bf16.bf16.f32 "
        "{%0,%1,%2,%3}, {%4,%5,%6,%7}, {%8,%9}, {%0,%1,%2,%3};"
        : "+f"(d[0]), "+f"(d[1]), "+f"(d[2]), "+f"(d[3])
        : "r"(a[0]), "r"(a[1]), "r"(a[2]), "r"(a[3]), "r"(b[0]), "r"(b[1]));
}

// ---------------- global scratch ----------------
__device__ float g_xpad[80u * 4u * 47u * 47u * 48u];
__device__ __nv_bfloat16 g_acth[80u * 12167u * 32u];  // [n][z23*y23*x23][ic], halo=0
__device__ __nv_bfloat16 g_actl[80u * 12167u * 32u];
__device__ __nv_bfloat16 g_w1h[250u * 32u * 16u];     // [kstep][n][k16]
__device__ __nv_bfloat16 g_w1l[250u * 32u * 16u];
__device__ float g_c1pre[80u * 6912u * 32u];          // conv1 pre-pool, channel-last
__device__ float g_buf1[80u * 32u * 11u * 11u * 12u];
__device__ float g_buf2[80u * 64u * 4u * 4u * 4u];
__device__ float g_feat[80u * 512u];
__device__ float g_mean1[16u * 512u];
__device__ float g_fc1[80u * 256u];
__device__ float g_mean2[16u * 256u];
__device__ float g_fc2[80u * 128u];
__device__ float g_mean3[16u * 128u];

__global__ void pad_x_kernel(const float* __restrict__ x, float* __restrict__ xp) {
    const size_t i = (size_t)blockIdx.x * blockDim.x + threadIdx.x;
    if (i >= 80u * 4u * 45u * 45u * 45u) return;
    const int xc = (int)(i % 45);
    size_t t = i / 45;
    const int y = (int)(t % 45); t /= 45;
    const int z = (int)(t % 45);
    const int nc = (int)(t / 45);
    xp[(((size_t)nc * 47 + (z + 1)) * 47 + (y + 1)) * 48 + (xc + 1)] = x[i];
}

// conv1 weights -> bf16 hi/lo in [kstep 250][n 32][k16]
__global__ void w1prep_kernel(const float* __restrict__ w,
                              __nv_bfloat16* __restrict__ wh, __nv_bfloat16* __restrict__ wl) {
    const int idx = blockIdx.x * 256 + threadIdx.x;
    if (idx >= 128000) return;
    const int kk = idx & 15, n = (idx >> 4) & 31, h = (idx >> 9) & 1, tap = idx >> 10;
    const int ic = h * 16 + kk;
    const float v = w[(n * 32 + ic) * 125 + tap];
    const __nv_bfloat16 hb = __float2bfloat16(v);
    wh[idx] = hb;
    wl[idx] = __float2bfloat16(v - __bfloat162float(hb));
}

// ---------------- conv0: scalar f32x2, writes channel-last bf16 hi/lo ----------------
// grid (21 pz, 16 cg, 80 n), block (7 tx, 21 py)
__global__ void conv0_kernel(const float* __restrict__ xp,
                             const float* __restrict__ w,
                             const float* __restrict__ bias,
                             const float* __restrict__ prelu,
                             __nv_bfloat16* __restrict__ acth,
                             __nv_bfloat16* __restrict__ actl) {
    const int pz = blockIdx.x, cg = blockIdx.y, n = blockIdx.z;
    const int tx = threadIdx.x, py = threadIdx.y;
    __shared__ __align__(16) ull ws[4 * 5 * 5 * 6];
    __shared__ float sb[2];
    __shared__ float sa;
    const int tid = py * 7 + tx;
    for (int i = tid; i < 500; i += 147) {
        const int ic = i / 125, rr = i % 125;
        const int kz = rr / 25, ky = (rr / 5) % 5, kx = rr % 5;
        ws[((ic * 5 + kz) * 5 + ky) * 6 + kx] =
            pack2(w[(cg * 2 + 0) * 500 + i] * (1.0f / 255.0f),
                  w[(cg * 2 + 1) * 500 + i] * (1.0f / 255.0f));
    }
    if (tid < 2) sb[tid] = bias[cg * 2 + tid];
    if (tid == 0) sa = prelu[0];
    __syncthreads();

    ull acc[3][2][2][2] = {};
    for (int ic = 0; ic < 4; ic++) {
        const float* base = xp + ((size_t)(n * 4 + ic)) * (47 * 47 * 48);
        for (int zin = 0; zin < 6; zin++) {
            const int zp = 2 * pz + zin;
            const bool oz0 = (zin <= 4), oz1 = (zin >= 1);
#pragma unroll
            for (int yin = 0; yin < 6; yin++) {
                const int yp = 2 * py + yin;
                const float2* rp = (const float2*)(base + ((size_t)zp * 47 + yp) * 48 + 6 * tx);
                float2 v[5];
#pragma unroll
                for (int j = 0; j < 5; j++) v[j] = __ldg(rp + j);
                ull p[10];
#pragma unroll
                for (int j = 0; j < 5; j++) {
                    p[2 * j + 0] = pack2(v[j].x, v[j].x);
                    p[2 * j + 1] = pack2(v[j].y, v[j].y);
                }
                const bool oy0 = (yin <= 4), oy1 = (yin >= 1);
#pragma unroll
                for (int oz = 0; oz < 2; oz++) {
                    if (oz ? !oz1 : !oz0) continue;
                    const int kz = zin - oz;
#pragma unroll
                    for (int oy = 0; oy < 2; oy++) {
                        if (oy ? !oy1 : !oy0) continue;
                        const int ky = yin - oy;
                        const ull* wr = &ws[((ic * 5 + kz) * 5 + ky) * 6];
                        const ulonglong2 wab = *(const ulonglong2*)wr;
                        const ulonglong2 wcd = *(const ulonglong2*)(wr + 2);
                        const ull W4 = wr[4];
#pragma unroll
                        for (int pxl = 0; pxl < 3; pxl++) {
#pragma unroll
                            for (int ox = 0; ox < 2; ox++) {
                                ull& A = acc[pxl][ox][oz][oy];
                                const int b = 2 * pxl + ox;
                                fma2(A, wab.x, p[b + 0]);
                                fma2(A, wab.y, p[b + 1]);
                                fma2(A, wcd.x, p[b + 2]);
                                fma2(A, wcd.y, p[b + 3]);
                                fma2(A, W4,    p[b + 4]);
                            }
                        }
                    }
                }
            }
        }
    }
#pragma unroll
    for (int pxl = 0; pxl < 3; pxl++) {
        float m0 = -CUDART_INF_F, m1 = -CUDART_INF_F;
#pragma unroll
        for (int ox = 0; ox < 2; ox++)
#pragma unroll
            for (int oz = 0; oz < 2; oz++)
#pragma unroll
                for (int oy = 0; oy < 2; oy++) {
                    const float2 v = unpack2(acc[pxl][ox][oz][oy]);
                    m0 = fmaxf(m0, v.x);
                    m1 = fmaxf(m1, v.y);
                }
        m0 += sb[0]; m1 += sb[1];
        const float v0 = (m0 >= 0.0f) ? m0 : sa * m0;
        const float v1 = (m1 >= 0.0f) ? m1 : sa * m1;
        const int px = 3 * tx + pxl;
        const size_t off = ((size_t)n * 12167u +
                            (((size_t)(pz + 1) * 23 + (py + 1)) * 23 + (px + 1))) * 32u + cg * 2;
        const __nv_bfloat16 h0 = __float2bfloat16(v0), h1 = __float2bfloat16(v1);
        const __nv_bfloat16 l0 = __float2bfloat16(v0 - __bfloat162float(h0));
        const __nv_bfloat16 l1 = __float2bfloat16(v1 - __bfloat162float(h1));
        __nv_bfloat162 ph; ph.x = h0; ph.y = h1;
        __nv_bfloat162 pl; pl.x = l0; pl.y = l1;
        *(__nv_bfloat162*)(acth + off) = ph;
        *(__nv_bfloat162*)(actl + off) = pl;
    }
}

// ---------------- conv1 via mma.sync m16n8k16 bf16 (hi/lo, 3 passes) ----------------
// grid (54, 80), block 128 (4 warps). Warp: M32 voxels x N32 channels, K=4000.
__global__ __launch_bounds__(128)
void conv1_mma_kernel(const __nv_bfloat16* __restrict__ acth,
                      const __nv_bfloat16* __restrict__ actl,
                      const __nv_bfloat16* __restrict__ w1h,
                      const __nv_bfloat16* __restrict__ w1l,
                      float* __restrict__ c1pre) {
    const int tile = blockIdx.x, n = blockIdx.y;
    const int tid = threadIdx.x, wid = tid >> 5, lane = tid & 31;
    const int g = lane >> 2, c = lane & 3;
    const int mstart = tile * 128 + wid * 32;

    const uint32_t* AH = (const uint32_t*)acth;
    const uint32_t* AL = (const uint32_t*)actl;
    const uint32_t* WH = (const uint32_t*)w1h;
    const uint32_t* WL = (const uint32_t*)w1l;

    uint32_t pb[2][2];
    int rowid[2][2];
#pragma unroll
    for (int t = 0; t < 2; t++)
#pragma unroll
        for (int j = 0; j < 2; j++) {
            int r = mstart + t * 16 + g + j * 8;
            rowid[t][j] = r;
            if (r > 6858) r = 6858;
            const int z = r / 361, rem = r % 361, y = rem / 19, x = rem % 19;
            pb[t][j] = (uint32_t)(n * 12167) + (uint32_t)((z * 23 + y) * 23 + x);
        }

    float d[2][4][4] = {};

    for (int kz = 0; kz < 5; kz++)
        for (int ky = 0; ky < 5; ky++)
#pragma unroll
            for (int kx = 0; kx < 5; kx++) {
                const uint32_t toff = (uint32_t)(kz * 529 + ky * 23 + kx);
                uint32_t ab[2][2];
#pragma unroll
                for (int t = 0; t < 2; t++)
#pragma unroll
                    for (int j = 0; j < 2; j++)
                        ab[t][j] = (pb[t][j] + toff) * 16u + (uint32_t)c;
                const int tap = (kz * 5 + ky) * 5 + kx;
#pragma unroll
                for (int h = 0; h < 2; h++) {
                    const uint32_t icadd = h * 8;
                    uint32_t ah[2][4], al[2][4];
#pragma unroll
                    for (int t = 0; t < 2; t++) {
                        ah[t][0] = __ldg(AH + ab[t][0] + icadd);
                        ah[t][1] = __ldg(AH + ab[t][1] + icadd);
                        ah[t][2] = __ldg(AH + ab[t][0] + icadd + 4);
                        ah[t][3] = __ldg(AH + ab[t][1] + icadd + 4);
                        al[t][0] = __ldg(AL + ab[t][0] + icadd);
                        al[t][1] = __ldg(AL + ab[t][1] + icadd);
                        al[t][2] = __ldg(AL + ab[t][0] + icadd + 4);
                        al[t][3] = __ldg(AL + ab[t][1] + icadd + 4);
                    }
                    const uint32_t s = (uint32_t)(tap * 2 + h);
#pragma unroll
                    for (int nb = 0; nb < 4; nb++) {
                        const uint32_t wr = (s * 32 + nb * 8 + g) * 8 + c;
                        uint32_t bh[2], bl[2];
                        bh[0] = __ldg(WH + wr);
                        bh[1] = __ldg(WH + wr + 4);
                        bl[0] = __ldg(WL + wr);
                        bl[1] = __ldg(WL + wr + 4);
#pragma unroll
                        for (int t = 0; t < 2; t++) {
                            mma_bf16(d[t][nb], ah[t], bh);
                            mma_bf16(d[t][nb], ah[t], bl);
                            mma_bf16(d[t][nb], al[t], bh);
                        }
                    }
                }
            }

#pragma unroll
    for (int t = 0; t < 2; t++)
#pragma unroll
        for (int nb = 0; nb < 4; nb++) {
            const int r0 = rowid[t][0], r1 = rowid[t][1];
            if (r0 < 6859) {
                float2 v; v.x = d[t][nb][0]; v.y = d[t][nb][1];
                *(float2*)(c1pre + ((size_t)n * 6912u + r0) * 32u + nb * 8 + 2 * c) = v;
            }
            if (r1 < 6859) {
                float2 v; v.x = d[t][nb][2]; v.y = d[t][nb][3];
                *(float2*)(c1pre + ((size_t)n * 6912u + r1) * 32u + nb * 8 + 2 * c) = v;
            }
        }
}

// pool 2x2x2 + bias + prelu -> padded buf1
__global__ void conv1_pool_kernel(const float* __restrict__ pre, const float* __restrict__ bias,
                                  const float* __restrict__ prelu, float* __restrict__ out) {
    int idx = blockIdx.x * 256 + threadIdx.x;
    if (idx >= 80 * 32 * 729) return;
    const int px = idx % 9; int t = idx / 9;
    const int py = t % 9; t /= 9;
    const int pz = t % 9; t /= 9;
    const int c = t % 32; const int n = t / 32;
    float m = -CUDART_INF_F;
#pragma unroll
    for (int dz = 0; dz < 2; dz++)
#pragma unroll
        for (int dy = 0; dy < 2; dy++)
#pragma unroll
            for (int dx = 0; dx < 2; dx++) {
                const int v = (2 * pz + dz) * 361 + (2 * py + dy) * 19 + (2 * px + dx);
                m = fmaxf(m, __ldg(pre + ((size_t)n * 6912u + v) * 32u + c));
            }
    m += bias[c];
    const float r = (m >= 0.0f) ? m : prelu[0] * m;
    out[((((size_t)n * 32 + c) * 11 + pz + 1) * 11 + py + 1) * 12 + px + 1] = r;
}

// ---------------- conv2: smem-staged slab, f32x2 ----------------
__global__ void conv2_kernel(const float* __restrict__ xpad,
                             const float* __restrict__ w,
                             const float* __restrict__ bias,
                             const float* __restrict__ prelu,
                             float* __restrict__ out) {
    const int bx = blockIdx.x, n = blockIdx.y;
    const int py = threadIdx.x, pz = threadIdx.y, c4 = threadIdx.z;
    __shared__ __align__(16) float ws[4 * 2048];
    __shared__ __align__(16) float slab[1452];
    __shared__ float sb[4];
    __shared__ float sa;
    const int tid = (c4 * 4 + pz) * 4 + py;
    for (int i = tid; i < 8192; i += 64) ws[i] = w[(size_t)bx * 8192 + i];
    if (tid < 4) sb[tid] = bias[bx * 4 + tid];
    if (tid == 0) sa = prelu[0];

    ull acc[4][2][2] = {};
    for (int ic = 0; ic < 32; ic++) {
        __syncthreads();
        const float4* src = (const float4*)(xpad + ((size_t)(n * 32 + ic)) * 1452);
        for (int i = tid; i < 363; i += 64) ((float4*)slab)[i] = __ldg(src + i);
        __syncthreads();
#pragma unroll
        for (int zin = 0; zin < 5; zin++) {
            const int zp = 2 * pz + zin;
            const bool oz0 = (zin <= 3), oz1 = (zin >= 1);
#pragma unroll
            for (int yin = 0; yin < 5; yin++) {
                const int yp = 2 * py + yin;
                const float* row = slab + (zp * 11 + yp) * 12;
                float in[11];
#pragma unroll
                for (int j = 0; j < 11; j++) in[j] = row[j];
                ull p[10];
#pragma unroll
                for (int i = 0; i < 10; i++) p[i] = pack2(in[i], in[i + 1]);
                const bool oy0 = (yin <= 3), oy1 = (yin >= 1);
#pragma unroll
                for (int oz = 0; oz < 2; oz++) {
                    if (oz ? !oz1 : !oz0) continue;
                    const int kz = zin - oz;
#pragma unroll
                    for (int oy = 0; oy < 2; oy++) {
                        if (oy ? !oy1 : !oy0) continue;
                        const int ky = yin - oy;
                        const float4 w4 = *(const float4*)&ws[((c4 * 32 + ic) * 16 + kz * 4 + ky) * 4];
                        const ull W0 = pack2(w4.x, w4.x), W1 = pack2(w4.y, w4.y),
                                  W2 = pack2(w4.z, w4.z), W3 = pack2(w4.w, w4.w);
#pragma unroll
                        for (int px = 0; px < 4; px++) {
                            ull& A = acc[px][oz][oy];
                            fma2(A, W0, p[2 * px + 0]);
                            fma2(A, W1, p[2 * px + 1]);
                            fma2(A, W2, p[2 * px + 2]);
                            fma2(A, W3, p[2 * px + 3]);
                        }
                    }
                }
            }
        }
    }
    const float b = sb[c4];
#pragma unroll
    for (int px = 0; px < 4; px++) {
        float m = -CUDART_INF_F;
#pragma unroll
        for (int oz = 0; oz < 2; oz++)
#pragma unroll
            for (int oy = 0; oy < 2; oy++) {
                const float2 v = unpack2(acc[px][oz][oy]);
                m = fmaxf(m, fmaxf(v.x, v.y));
            }
        m += b;
        const float v = (m >= 0.0f) ? m : sa * m;
        out[(((size_t)(n * 64 + bx * 4 + c4) * 4 + pz) * 4 + py) * 4 + px] = v;
    }
}

__global__ void conv3_kernel(const float* __restrict__ x,
                             const float* __restrict__ w,
                             const float* __restrict__ bias,
                             const float* __restrict__ prelu,
                             float* __restrict__ feat) {
    const int n = blockIdx.x;
    const int tid = threadIdx.x;
    __shared__ float sin[64 * 64];
    for (int i = tid; i < 4096; i += 512) sin[i] = x[(size_t)n * 4096 + i];
    __syncthreads();
    const int c = tid >> 3, s = tid & 7;
    const int oz = s >> 2, oy = (s >> 1) & 1, ox = s & 1;
    float acc = bias[c];
    const float* wc = w + (size_t)c * 64 * 27;
    for (int ic = 0; ic < 64; ic++) {
        const float* si = sin + ic * 64;
        const float* wi = wc + ic * 27;
#pragma unroll
        for (int kz = 0; kz < 3; kz++)
#pragma unroll
            for (int ky = 0; ky < 3; ky++)
#pragma unroll
                for (int kx = 0; kx < 3; kx++)
                    acc = fmaf(__ldg(wi + (kz * 3 + ky) * 3 + kx),
                               si[(oz + kz) * 16 + (oy + ky) * 4 + (ox + kx)], acc);
    }
    const float a = prelu[0];
    feat[(size_t)n * 512 + c * 8 + s] = (acc >= 0.0f) ? acc : a * acc;
}

__global__ void mean_kernel(const float* __restrict__ feat, float* __restrict__ mean, int D) {
    const int b = blockIdx.x, i = threadIdx.x;
    float s = 0.0f;
    for (int a = 0; a < 5; a++) s += feat[((size_t)(b * 5 + a)) * D + i];
    mean[(size_t)b * D + i] = s * (1.0f / 5.0f);
}

__global__ void commfc_kernel(const float* __restrict__ feat,
                              const float* __restrict__ mean,
                              const float* __restrict__ w,
                              const float* __restrict__ bias,
                              const float* __restrict__ prelu,
                              float* __restrict__ out, int D, int O) {
    const int bx = blockIdx.x;
    const int b = bx / 5, a = bx % 5;
    const int warp = threadIdx.x >> 5, lane = threadIdx.x & 31;
    const int o = blockIdx.y * 8 + warp;
    if (o >= O) return;
    const int D4 = D >> 2;
    const float4* fp = (const float4*)(feat + (size_t)bx * D);
    const float4* mp = (const float4*)(mean + (size_t)b * D);
    const float4* wp = (const float4*)(w + ((size_t)a * O + o) * (2 * D));
    float acc = 0.0f;
    for (int i = lane; i < D4; i += 32) {
        const float4 f = fp[i];
        const float4 wv = __ldg(wp + i);
        acc += f.x * wv.x + f.y * wv.y + f.z * wv.z + f.w * wv.w;
    }
    for (int i = lane; i < D4; i += 32) {
        const float4 m = mp[i];
        const float4 wv = __ldg(wp + D4 + i);
        acc += m.x * wv.x + m.y * wv.y + m.z * wv.z + m.w * wv.w;
    }
#pragma unroll
    for (int s = 16; s > 0; s >>= 1) acc += __shfl_xor_sync(0xffffffffu, acc, s);
    if (lane == 0) {
        acc += bias[a * O + o];
        if (prelu) { const float al = prelu[0]; acc = (acc >= 0.0f) ? acc : al * acc; }
        out[(size_t)bx * O + o] = acc;
    }
}

extern "C" void kernel_launch(void* const* d_in, const int* in_sizes, int n_in,
                              void* d_out, int out_size) {
    const float* x       = (const float*)d_in[0];
    const float* conv0_w = (const float*)d_in[1];
    const float* conv0_b = (const float*)d_in[2];
    const float* prelu0  = (const float*)d_in[3];
    const float* conv1_w = (const float*)d_in[4];
    const float* conv1_b = (const float*)d_in[5];
    const float* prelu1  = (const float*)d_in[6];
    const float* conv2_w = (const float*)d_in[7];
    const float* conv2_b = (const float*)d_in[8];
    const float* prelu2  = (const float*)d_in[9];
    const float* conv3_w = (const float*)d_in[10];
    const float* conv3_b = (const float*)d_in[11];
    const float* prelu3  = (const float*)d_in[12];
    const float* fc1_w   = (const float*)d_in[13];
    const float* fc1_b   = (const float*)d_in[14];
    const float* prelu4  = (const float*)d_in[15];
    const float* fc2_w   = (const float*)d_in[16];
    const float* fc2_b   = (const float*)d_in[17];
    const float* prelu5  = (const float*)d_in[18];
    const float* fc3_w   = (const float*)d_in[19];
    const float* fc3_b   = (const float*)d_in[20];
    float* out = (float*)d_out;

    float *xpad, *c1pre, *buf1, *buf2, *feat, *mean1, *fc1, *mean2, *fc2, *mean3;
    __nv_bfloat16 *acth, *actl, *w1h, *w1l;
    cudaGetSymbolAddress((void**)&xpad,  g_xpad);
    cudaGetSymbolAddress((void**)&acth,  g_acth);
    cudaGetSymbolAddress((void**)&actl,  g_actl);
    cudaGetSymbolAddress((void**)&w1h,   g_w1h);
    cudaGetSymbolAddress((void**)&w1l,   g_w1l);
    cudaGetSymbolAddress((void**)&c1pre, g_c1pre);
    cudaGetSymbolAddress((void**)&buf1,  g_buf1);
    cudaGetSymbolAddress((void**)&buf2,  g_buf2);
    cudaGetSymbolAddress((void**)&feat,  g_feat);
    cudaGetSymbolAddress((void**)&mean1, g_mean1);
    cudaGetSymbolAddress((void**)&fc1,   g_fc1);
    cudaGetSymbolAddress((void**)&mean2, g_mean2);
    cudaGetSymbolAddress((void**)&fc2,   g_fc2);
    cudaGetSymbolAddress((void**)&mean3, g_mean3);

    const size_t xtotal = 80u * 4u * 45u * 45u * 45u;
    pad_x_kernel<<<(unsigned)((xtotal + 255) / 256), 256>>>(x, xpad);
    w1prep_kernel<<<500, 256>>>(conv1_w, w1h, w1l);

    conv0_kernel<<<dim3(21, 16, NN), dim3(7, 21)>>>(xpad, conv0_w, conv0_b, prelu0, acth, actl);
    conv1_mma_kernel<<<dim3(54, NN), 128>>>(acth, actl, w1h, w1l, c1pre);
    conv1_pool_kernel<<<(80 * 32 * 729 + 255) / 256, 256>>>(c1pre, conv1_b, prelu1, buf1);
    conv2_kernel<<<dim3(16, NN), dim3(4, 4, 4)>>>(buf1, conv2_w, conv2_b, prelu2, buf2);
    conv3_kernel<<<NN, 512>>>(buf2, conv3_w, conv3_b, prelu3, feat);

    mean_kernel<<<16, 512>>>(feat, mean1, 512);
    commfc_kernel<<<dim3(NN, 32), 256>>>(feat, mean1, fc1_w, fc1_b, prelu4, fc1, 512, 256);
    mean_kernel<<<16, 256>>>(fc1, mean2, 256);
    commfc_kernel<<<dim3(NN, 16), 256>>>(fc1, mean2, fc2_w, fc2_b, prelu5, fc2, 256, 128);
    mean_kernel<<<16, 128>>>(fc2, mean3, 128);
    commfc_kernel<<<dim3(NN, 1), 256>>>(fc2, mean3, fc3_w, fc3_b, nullptr, out, 128, 6);
}